// round 5
// baseline (speedup 1.0000x reference)
#include <cuda_runtime.h>
#include <math.h>

// ---------------- problem constants ----------------
#define NB     64      // batch
#define TT     2000
#define TW     10      // attention window (t in [0, 9])
#define ENC    512
#define ATT    256
#define DEC    256
#define SPK    64
#define OOUT   80
#define HID    1024    // 4*DEC
#define G4     4096    // 4*HID
#define INL    832     // ENC + DEC + SPK
#define CATL   1536    // HID + ENC
#define OUTM   160     // O*R
#define XCATK  144     // O + SPK
#define SK_ATT 4
#define SK_L0  4       // 832/4 = 208 (13 k-tiles of 16)
#define SK_L1  8       // 1024/8 = 128 (8 k-tiles of 16)

// packed fp32x2 helpers (sm_103a)
#define FMA_F32X2(d, a, b, c) \
    asm("fma.rn.f32x2 %0, %1, %2, %3;" : "=l"(d) : "l"(a), "l"(b), "l"(c))
#define PACK_DUP(d, f) \
    asm("mov.b64 %0, {%1, %1};" : "=l"(d) : "r"(__float_as_uint(f)))

// ---------------- scratch (device globals; no allocs allowed) ----------------
__device__ float d_xcat  [NB * XCATK];
__device__ float d_s1    [NB * DEC];
__device__ float d_p1    [NB * 512];
__device__ float d_pre   [NB * DEC];
__device__ float d_sp    [NB * ENC];
__device__ float d_spkatt[NB * ATT];
__device__ float d_X2    [NB * TW * ENC];
__device__ float d_C2p   [SK_ATT * NB * TW * ATT];
__device__ float d_logit [NB * TW];
__device__ float d_inlstm[NB * INL];
__device__ float d_g0p   [SK_L0 * NB * G4];
__device__ float d_h1    [NB * HID];
__device__ float d_g1p   [SK_L1 * NB * G4];
__device__ float d_deccat[NB * CATL];

// ---------------- kernel 1: gathers / tiny elementwise prep ----------------
__global__ void prep0_kernel(const float* __restrict__ input_dec,
                             const float* __restrict__ spkr,
                             const float* __restrict__ speed,
                             const float* __restrict__ W_sp1,
                             const float* __restrict__ b_sp1,
                             const float* __restrict__ input_enc) {
    int i = blockIdx.x * blockDim.x + threadIdx.x;
    const int N_XCAT = NB * XCATK;             // 9216
    const int N_S1   = NB * DEC;               // 16384
    const int N_X2   = NB * TW * ENC;          // 327680
    if (i < N_XCAT) {
        int n = i / XCATK, c = i % XCATK;
        d_xcat[i] = (c < OOUT) ? input_dec[n * OOUT + c] : spkr[n * SPK + (c - OOUT)];
        return;
    }
    i -= N_XCAT;
    if (i < N_S1) {
        int n = i / DEC, d = i % DEC;
        float v = speed[n] * W_sp1[d] + b_sp1[d];
        d_s1[i] = v > 0.f ? v : 0.f;
        return;
    }
    i -= N_S1;
    if (i < N_X2) {
        int r = i / ENC, k = i % ENC;
        int n = r / TW, t = r % TW;
        d_X2[i] = input_enc[((size_t)n * TT + t) * ENC + k];
    }
}

// ---------------- small fused linear: C[n,m] = act(X[n,:]·W[m,:] + b[m]) ----
// grid = M blocks, 64 threads (one per batch row). W row staged in smem.
// act: 0 none, 1 relu, 2 tanh, 3 softsign
__global__ void lin_small_kernel(const float* __restrict__ X,
                                 const float* __restrict__ W,
                                 const float* __restrict__ b,
                                 float* __restrict__ C,
                                 int K, int M, int act) {
    __shared__ float ws[1536];
    int m = blockIdx.x;
    int n = threadIdx.x;
    for (int k = n; k < K; k += 64) ws[k] = W[(size_t)m * K + k];
    __syncthreads();
    const float4* x4 = (const float4*)(X + (size_t)n * K);
    float a0 = 0.f, a1 = 0.f, a2 = 0.f, a3 = 0.f;
    int K4 = K >> 2;
    for (int k4 = 0; k4 < K4; k4++) {
        float4 xv = x4[k4];
        a0 += xv.x * ws[4 * k4 + 0];
        a1 += xv.y * ws[4 * k4 + 1];
        a2 += xv.z * ws[4 * k4 + 2];
        a3 += xv.w * ws[4 * k4 + 3];
    }
    float acc = (a0 + a1) + (a2 + a3);
    if (b) acc += b[m];
    if (act == 1) acc = acc > 0.f ? acc : 0.f;
    else if (act == 2) acc = tanhf(acc);
    else if (act == 3) acc = acc / (1.f + fabsf(acc));
    C[(size_t)n * M + m] = acc;
}

// ---------------- big GEMM (split-K partials, packed f32x2 math) -----------
// Cp[s][n,m] = sum_{k in split s} X[n,k]*W[m,k]
// 64n x 64m tile per block, 16x16 threads, each thread: rows 4*ty..+3 (consec),
// cols 4*tx..+3 (consec). K-major smem; FFMA2 inner loop.
__global__ void gemm64_kernel(const float* __restrict__ X,
                              const float* __restrict__ W,
                              float* __restrict__ Cp,
                              int NN, int M, int K) {
    __shared__ float Xs[16][68];   // 68-float row stride: 272B, 16B-aligned
    __shared__ float Ws[16][68];
    int S  = gridDim.z;
    int nk = K / S;
    int ks0 = nk * blockIdx.z;
    int m0 = blockIdx.x * 64;
    int n0 = blockIdx.y * 64;
    int tx = threadIdx.x, ty = threadIdx.y;
    int tid = ty * 16 + tx;
    int lr = tid >> 2;            // 0..63
    int lk = (tid & 3) * 4;       // 0,4,8,12
    const float* Xp = X + (size_t)(n0 + lr) * K + ks0 + lk;
    const float* Wp = W + (size_t)(m0 + lr) * K + ks0 + lk;

    unsigned long long acc[4][2];
#pragma unroll
    for (int i = 0; i < 4; i++) { acc[i][0] = 0ull; acc[i][1] = 0ull; }

    for (int kt = 0; kt < nk; kt += 16) {
        float4 xv = *(const float4*)(Xp + kt);
        float4 wv = *(const float4*)(Wp + kt);
        __syncthreads();
        Xs[lk + 0][lr] = xv.x; Xs[lk + 1][lr] = xv.y;
        Xs[lk + 2][lr] = xv.z; Xs[lk + 3][lr] = xv.w;
        Ws[lk + 0][lr] = wv.x; Ws[lk + 1][lr] = wv.y;
        Ws[lk + 2][lr] = wv.z; Ws[lk + 3][lr] = wv.w;
        __syncthreads();
#pragma unroll
        for (int k = 0; k < 16; k++) {
            float4 xr = *(const float4*)&Xs[k][4 * ty];          // broadcast
            unsigned long long w01 = *(const unsigned long long*)&Ws[k][4 * tx];
            unsigned long long w23 = *(const unsigned long long*)&Ws[k][4 * tx + 2];
            unsigned long long xx;
            PACK_DUP(xx, xr.x);
            FMA_F32X2(acc[0][0], xx, w01, acc[0][0]);
            FMA_F32X2(acc[0][1], xx, w23, acc[0][1]);
            PACK_DUP(xx, xr.y);
            FMA_F32X2(acc[1][0], xx, w01, acc[1][0]);
            FMA_F32X2(acc[1][1], xx, w23, acc[1][1]);
            PACK_DUP(xx, xr.z);
            FMA_F32X2(acc[2][0], xx, w01, acc[2][0]);
            FMA_F32X2(acc[2][1], xx, w23, acc[2][1]);
            PACK_DUP(xx, xr.w);
            FMA_F32X2(acc[3][0], xx, w01, acc[3][0]);
            FMA_F32X2(acc[3][1], xx, w23, acc[3][1]);
        }
    }
    size_t base = (size_t)blockIdx.z * NN * M;
#pragma unroll
    for (int i = 0; i < 4; i++) {
        float4 o;
        unsigned int u0, u1;
        asm("mov.b64 {%0, %1}, %2;" : "=r"(u0), "=r"(u1) : "l"(acc[i][0]));
        o.x = __uint_as_float(u0); o.y = __uint_as_float(u1);
        asm("mov.b64 {%0, %1}, %2;" : "=r"(u0), "=r"(u1) : "l"(acc[i][1]));
        o.z = __uint_as_float(u0); o.w = __uint_as_float(u1);
        *(float4*)&Cp[base + (size_t)(n0 + 4 * ty + i) * M + m0 + 4 * tx] = o;
    }
}

// ---------------- logit: per (n,t) reduce over ATT ----------------
__global__ void logit_kernel(const float* __restrict__ b_enc,
                             const float* __restrict__ conv_prev,
                             const float* __restrict__ W_speed_att,
                             const float* __restrict__ speed,
                             const float* __restrict__ W_proj,
                             const float* __restrict__ b_proj) {
    int nt = blockIdx.x;         // n*10 + t
    int n = nt / TW, t = nt % TW;
    int a = threadIdx.x;         // 0..255
    float v = b_enc[a];
#pragma unroll
    for (int s = 0; s < SK_ATT; s++)
        v += d_C2p[(size_t)s * NB * TW * ATT + (size_t)nt * ATT + a];
    float e = v / (1.f + fabsf(v))
            + d_spkatt[n * ATT + a]
            + conv_prev[a * 31 + (15 - t)]
            + speed[n] * W_speed_att[a];
    float p = tanhf(e) * W_proj[a];
#pragma unroll
    for (int off = 16; off > 0; off >>= 1)
        p += __shfl_down_sync(0xffffffffu, p, off);
    __shared__ float red[8];
    int lane = a & 31, w = a >> 5;
    if (lane == 0) red[w] = p;
    __syncthreads();
    if (a == 0) {
        float tot = 0.f;
#pragma unroll
        for (int i = 0; i < 8; i++) tot += red[i];
        d_logit[nt] = tot + b_proj[0];
    }
}

// ---------------- softmax over window + context + concat staging -----------
__global__ void smax_ctx_kernel(const int* __restrict__ lengths,
                                const float* __restrict__ spkr,
                                float* __restrict__ out_ctx,
                                int wctx) {
    int n = blockIdx.x;
    int tid = threadIdx.x;   // 256
    int len = lengths[n];
    int len1 = (len > 1 ? len : 1) - 1;
    int hi = len1 < (TW - 1) ? len1 : (TW - 1);
    float lg[TW];
#pragma unroll
    for (int t = 0; t < TW; t++) lg[t] = d_logit[n * TW + t];
    float m = -1e30f;
#pragma unroll
    for (int t = 0; t < TW; t++) if (t <= hi && lg[t] > m) m = lg[t];
    float att[TW]; float s = 0.f;
#pragma unroll
    for (int t = 0; t < TW; t++) {
        float w = (t <= hi) ? __expf(lg[t] - m) : 0.f;
        att[t] = w; s += w;
    }
    float inv = 1.f / fmaxf(s, 1e-12f);
#pragma unroll
    for (int t = 0; t < TW; t++) att[t] *= inv;

#pragma unroll
    for (int it = 0; it < 2; it++) {
        int e = tid + it * 256;
        float spv = d_sp[n * ENC + e];
        float acc = 0.f;
#pragma unroll
        for (int t = 0; t < TW; t++)
            acc += att[t] * (d_X2[((size_t)n * TW + t) * ENC + e] + spv);
        d_inlstm[n * INL + DEC + e]  = acc;        // [pre | ctx | spkr]
        d_deccat[n * CATL + HID + e] = acc;        // [h2 | ctx]
        if (wctx) out_ctx[n * ENC + e] = acc;
    }
    if (tid < DEC) d_inlstm[n * INL + tid] = d_pre[n * DEC + tid];
    if (tid < SPK) d_inlstm[n * INL + DEC + ENC + tid] = spkr[n * SPK + tid];
}

// ---------------- LSTM gate (zero initial state => f gate dead) ------------
// h = sigmoid(o) * tanh( sigmoid(i) * tanh(g) )
__global__ void lstm_gate_kernel(const float* __restrict__ gp,
                                 const float* __restrict__ bih,
                                 const float* __restrict__ bhh,
                                 float* __restrict__ hout,
                                 int out_stride, int S) {
    int idx = blockIdx.x * blockDim.x + threadIdx.x;   // n*HID + j
    if (idx >= NB * HID) return;
    int n = idx / HID, j = idx % HID;
    size_t row = (size_t)n * G4;
    float gi = bih[j]          + bhh[j];
    float gg = bih[2*HID + j]  + bhh[2*HID + j];
    float go = bih[3*HID + j]  + bhh[3*HID + j];
    for (int s = 0; s < S; s++) {
        size_t base = (size_t)s * NB * G4 + row;
        gi += gp[base + j];
        gg += gp[base + 2*HID + j];
        go += gp[base + 3*HID + j];
    }
    float si = 1.f / (1.f + __expf(-gi));
    float so = 1.f / (1.f + __expf(-go));
    float h = so * tanhf(si * tanhf(gg));
    hout[(size_t)n * out_stride + j] = h;
}

extern "C" void kernel_launch(void* const* d_in, const int* in_sizes, int n_in,
                              void* d_out, int out_size) {
    const float* input_enc   = (const float*)d_in[0];
    const float* input_dec   = (const float*)d_in[1];
    const float* spkr        = (const float*)d_in[2];
    const int*   lengths     = (const int*)  d_in[3];
    const float* speed       = (const float*)d_in[4];
    const float* W_enc       = (const float*)d_in[5];
    const float* b_enc       = (const float*)d_in[6];
    const float* W_spkr      = (const float*)d_in[7];
    const float* conv_prev   = (const float*)d_in[8];
    const float* W_speed_att = (const float*)d_in[9];
    const float* W_proj      = (const float*)d_in[10];
    const float* b_proj      = (const float*)d_in[11];
    const float* W_sp1       = (const float*)d_in[12];
    const float* b_sp1       = (const float*)d_in[13];
    const float* W_sp2       = (const float*)d_in[14];
    const float* b_sp2       = (const float*)d_in[15];
    const float* W_p1        = (const float*)d_in[16];
    const float* b_p1        = (const float*)d_in[17];
    const float* W_p2        = (const float*)d_in[18];
    const float* b_p2        = (const float*)d_in[19];
    const float* Wih0        = (const float*)d_in[20];
    const float* bih0        = (const float*)d_in[22];
    const float* bhh0        = (const float*)d_in[23];
    const float* Wih1        = (const float*)d_in[24];
    const float* bih1        = (const float*)d_in[26];
    const float* bhh1        = (const float*)d_in[27];
    const float* W_out       = (const float*)d_in[28];
    const float* b_out       = (const float*)d_in[29];

    float* out = (float*)d_out;
    int wctx = (out_size >= NB * OUTM + NB * ENC) ? 1 : 0;

    // resolve scratch addresses once per process (fixed device-global
    // addresses; deterministic, capture-safe, no stream interaction)
    static float *p_xcat = nullptr, *p_s1, *p_p1, *p_pre, *p_sp, *p_spk, *p_X2,
                 *p_inl, *p_g0, *p_h1, *p_g1, *p_cat, *p_C2;
    if (!p_xcat) {
        cudaGetSymbolAddress((void**)&p_xcat, d_xcat);
        cudaGetSymbolAddress((void**)&p_s1,   d_s1);
        cudaGetSymbolAddress((void**)&p_p1,   d_p1);
        cudaGetSymbolAddress((void**)&p_pre,  d_pre);
        cudaGetSymbolAddress((void**)&p_sp,   d_sp);
        cudaGetSymbolAddress((void**)&p_spk,  d_spkatt);
        cudaGetSymbolAddress((void**)&p_X2,   d_X2);
        cudaGetSymbolAddress((void**)&p_inl,  d_inlstm);
        cudaGetSymbolAddress((void**)&p_g0,   d_g0p);
        cudaGetSymbolAddress((void**)&p_h1,   d_h1);
        cudaGetSymbolAddress((void**)&p_g1,   d_g1p);
        cudaGetSymbolAddress((void**)&p_cat,  d_deccat);
        cudaGetSymbolAddress((void**)&p_C2,   d_C2p);
    }

    int prep_threads = NB * XCATK + NB * DEC + NB * TW * ENC;
    prep0_kernel<<<(prep_threads + 255) / 256, 256>>>(input_dec, spkr, speed,
                                                      W_sp1, b_sp1, input_enc);

    // prenet + speed-proj + spkr attention bias (small linears)
    lin_small_kernel<<<512, 64>>>(p_xcat, W_p1, b_p1, p_p1, XCATK, 512, 1);
    lin_small_kernel<<<256, 64>>>(p_p1,  W_p2, b_p2, p_pre, 512, DEC, 1);
    lin_small_kernel<<<512, 64>>>(p_s1,  W_sp2, b_sp2, p_sp, DEC, ENC, 2);
    lin_small_kernel<<<256, 64>>>(spkr,  W_spkr, nullptr, p_spk, SPK, ATT, 3);

    // attention-energy GEMM on the 10-step window: [640,512]x[256,512]
    gemm64_kernel<<<dim3(ATT / 64, (NB * TW) / 64, SK_ATT), dim3(16, 16)>>>(
        p_X2, W_enc, p_C2, NB * TW, ATT, ENC);

    logit_kernel<<<NB * TW, 256>>>(b_enc, conv_prev, W_speed_att, speed, W_proj, b_proj);

    smax_ctx_kernel<<<NB, 256>>>(lengths, spkr, out + NB * OUTM, wctx);

    // LSTM layer 0: [64,832] x [4096,832]
    gemm64_kernel<<<dim3(G4 / 64, 1, SK_L0), dim3(16, 16)>>>(p_inl, Wih0, p_g0, NB, G4, INL);
    lstm_gate_kernel<<<(NB * HID + 255) / 256, 256>>>(p_g0, bih0, bhh0, p_h1, HID, SK_L0);

    // LSTM layer 1: [64,1024] x [4096,1024]
    gemm64_kernel<<<dim3(G4 / 64, 1, SK_L1), dim3(16, 16)>>>(p_h1, Wih1, p_g1, NB, G4, HID);
    lstm_gate_kernel<<<(NB * HID + 255) / 256, 256>>>(p_g1, bih1, bhh1, p_cat, CATL, SK_L1);

    // output linear: [64,1536] x [160,1536] -> d_out[0:10240]
    lin_small_kernel<<<OUTM, 64>>>(p_cat, W_out, b_out, out, CATL, OUTM, 0);
}

// round 10
// speedup vs baseline: 1.6584x; 1.6584x over previous
#include <cuda_runtime.h>
#include <math.h>

// ---------------- problem constants ----------------
#define NB     64      // batch
#define TT     2000
#define TW     10      // attention window (t in [0, 9])
#define ENC    512
#define ATT    256
#define DEC    256
#define SPK    64
#define OOUT   80
#define HID    1024    // 4*DEC
#define G4     4096    // 4*HID
#define INL    832     // ENC + DEC + SPK
#define CATL   1536    // HID + ENC
#define OUTM   160     // O*R
#define XCATK  144     // O + SPK
#define SK_ATT 4       // 512/4  = 128
#define SK_L0  13      // 832/13 = 64
#define SK_L1  8       // 1024/8 = 128

// packed fp32x2 helpers (sm_103a)
#define FMA_F32X2(d, a, b, c) \
    asm("fma.rn.f32x2 %0, %1, %2, %3;" : "=l"(d) : "l"(a), "l"(b), "l"(c))
#define PACK_DUP(d, f) \
    asm("mov.b64 %0, {%1, %1};" : "=l"(d) : "r"(__float_as_uint(f)))

// ---------------- scratch (device globals; no allocs allowed) ----------------
__device__ float d_xcat  [NB * XCATK];
__device__ float d_s1    [NB * DEC];
__device__ float d_p1    [NB * 512];
__device__ float d_sp    [NB * ENC];
__device__ float d_spkatt[NB * ATT];
__device__ float d_X2    [NB * TW * ENC];
__device__ float d_C2p   [SK_ATT * NB * TW * ATT];
__device__ float d_inlstm[NB * INL];
__device__ float d_g0p   [SK_L0 * NB * G4];
__device__ float d_h1    [NB * HID];
__device__ float d_g1p   [SK_L1 * NB * G4];
__device__ float d_deccat[NB * CATL];

// ---------------- kernel 1: gathers / tiny elementwise prep ----------------
// builds xcat, s1, X2 gather, and stages spkr into d_inlstm tail
__global__ void prep0_kernel(const float* __restrict__ input_dec,
                             const float* __restrict__ spkr,
                             const float* __restrict__ speed,
                             const float* __restrict__ W_sp1,
                             const float* __restrict__ b_sp1,
                             const float* __restrict__ input_enc) {
    int i = blockIdx.x * blockDim.x + threadIdx.x;
    const int N_XCAT = NB * XCATK;             // 9216
    const int N_S1   = NB * DEC;               // 16384
    const int N_SPK  = NB * SPK;               // 4096
    const int N_X2   = NB * TW * ENC;          // 327680
    if (i < N_XCAT) {
        int n = i / XCATK, c = i % XCATK;
        d_xcat[i] = (c < OOUT) ? input_dec[n * OOUT + c] : spkr[n * SPK + (c - OOUT)];
        return;
    }
    i -= N_XCAT;
    if (i < N_S1) {
        int n = i / DEC, d = i % DEC;
        float v = speed[n] * W_sp1[d] + b_sp1[d];
        d_s1[i] = v > 0.f ? v : 0.f;
        return;
    }
    i -= N_S1;
    if (i < N_SPK) {
        int n = i / SPK, c = i % SPK;
        d_inlstm[n * INL + DEC + ENC + c] = spkr[i];
        return;
    }
    i -= N_SPK;
    if (i < N_X2) {
        int r = i / ENC, k = i % ENC;
        int n = r / TW, t = r % TW;
        d_X2[i] = input_enc[((size_t)n * TT + t) * ENC + k];
    }
}

// ---------------- warp-per-output linear -----------------------------------
// C[n*ldc + m] = act(X[n,:]·W[m,:] + b[m])
// grid (M/8, NB/4); block 256 = 8 warps. warp w -> m = bx*8+w; handles 4 n's.
// lanes parallel over K (coalesced), shuffle-reduce, lane0 stores.
// act: 0 none, 1 relu, 2 tanh, 3 softsign
__global__ void linW_kernel(const float* __restrict__ X,
                            const float* __restrict__ W,
                            const float* __restrict__ b,
                            float* __restrict__ C,
                            int K, int M, int ldc, int act) {
    int warp = threadIdx.x >> 5, lane = threadIdx.x & 31;
    int m  = blockIdx.x * 8 + warp;
    int n0 = blockIdx.y * 4;
    const float* wrow = W + (size_t)m * K;
    float a0 = 0.f, a1 = 0.f, a2 = 0.f, a3 = 0.f;
    if ((K & 127) == 0) {
        const float* x0 = X + (size_t)(n0 + 0) * K;
        const float* x1 = X + (size_t)(n0 + 1) * K;
        const float* x2 = X + (size_t)(n0 + 2) * K;
        const float* x3 = X + (size_t)(n0 + 3) * K;
        for (int k = lane * 4; k < K; k += 128) {
            float4 wv = *(const float4*)(wrow + k);
            float4 v;
            v = *(const float4*)(x0 + k);
            a0 += v.x * wv.x + v.y * wv.y + v.z * wv.z + v.w * wv.w;
            v = *(const float4*)(x1 + k);
            a1 += v.x * wv.x + v.y * wv.y + v.z * wv.z + v.w * wv.w;
            v = *(const float4*)(x2 + k);
            a2 += v.x * wv.x + v.y * wv.y + v.z * wv.z + v.w * wv.w;
            v = *(const float4*)(x3 + k);
            a3 += v.x * wv.x + v.y * wv.y + v.z * wv.z + v.w * wv.w;
        }
    } else {
        for (int k = lane; k < K; k += 32) {
            float wv = wrow[k];
            a0 += X[(size_t)(n0 + 0) * K + k] * wv;
            a1 += X[(size_t)(n0 + 1) * K + k] * wv;
            a2 += X[(size_t)(n0 + 2) * K + k] * wv;
            a3 += X[(size_t)(n0 + 3) * K + k] * wv;
        }
    }
#pragma unroll
    for (int off = 16; off > 0; off >>= 1) {
        a0 += __shfl_down_sync(0xffffffffu, a0, off);
        a1 += __shfl_down_sync(0xffffffffu, a1, off);
        a2 += __shfl_down_sync(0xffffffffu, a2, off);
        a3 += __shfl_down_sync(0xffffffffu, a3, off);
    }
    if (lane == 0) {
        float bb = b ? b[m] : 0.f;
        float r[4] = {a0 + bb, a1 + bb, a2 + bb, a3 + bb};
#pragma unroll
        for (int i = 0; i < 4; i++) {
            float v = r[i];
            if (act == 1) v = v > 0.f ? v : 0.f;
            else if (act == 2) v = tanhf(v);
            else if (act == 3) v = v / (1.f + fabsf(v));
            C[(size_t)(n0 + i) * ldc + m] = v;
        }
    }
}

// ---------------- big GEMM (split-K partials, packed f32x2 math) -----------
// Cp[s][n,m] = sum_{k in split s} X[n,k]*W[m,k]
__global__ void gemm64_kernel(const float* __restrict__ X,
                              const float* __restrict__ W,
                              float* __restrict__ Cp,
                              int NN, int M, int K) {
    __shared__ float Xs[16][68];
    __shared__ float Ws[16][68];
    int S  = gridDim.z;
    int nk = K / S;
    int ks0 = nk * blockIdx.z;
    int m0 = blockIdx.x * 64;
    int n0 = blockIdx.y * 64;
    int tx = threadIdx.x, ty = threadIdx.y;
    int tid = ty * 16 + tx;
    int lr = tid >> 2;            // 0..63
    int lk = (tid & 3) * 4;       // 0,4,8,12
    const float* Xp = X + (size_t)(n0 + lr) * K + ks0 + lk;
    const float* Wp = W + (size_t)(m0 + lr) * K + ks0 + lk;

    unsigned long long acc[4][2];
#pragma unroll
    for (int i = 0; i < 4; i++) { acc[i][0] = 0ull; acc[i][1] = 0ull; }

    for (int kt = 0; kt < nk; kt += 16) {
        float4 xv = *(const float4*)(Xp + kt);
        float4 wv = *(const float4*)(Wp + kt);
        __syncthreads();
        Xs[lk + 0][lr] = xv.x; Xs[lk + 1][lr] = xv.y;
        Xs[lk + 2][lr] = xv.z; Xs[lk + 3][lr] = xv.w;
        Ws[lk + 0][lr] = wv.x; Ws[lk + 1][lr] = wv.y;
        Ws[lk + 2][lr] = wv.z; Ws[lk + 3][lr] = wv.w;
        __syncthreads();
#pragma unroll
        for (int k = 0; k < 16; k++) {
            float4 xr = *(const float4*)&Xs[k][4 * ty];
            unsigned long long w01 = *(const unsigned long long*)&Ws[k][4 * tx];
            unsigned long long w23 = *(const unsigned long long*)&Ws[k][4 * tx + 2];
            unsigned long long xx;
            PACK_DUP(xx, xr.x);
            FMA_F32X2(acc[0][0], xx, w01, acc[0][0]);
            FMA_F32X2(acc[0][1], xx, w23, acc[0][1]);
            PACK_DUP(xx, xr.y);
            FMA_F32X2(acc[1][0], xx, w01, acc[1][0]);
            FMA_F32X2(acc[1][1], xx, w23, acc[1][1]);
            PACK_DUP(xx, xr.z);
            FMA_F32X2(acc[2][0], xx, w01, acc[2][0]);
            FMA_F32X2(acc[2][1], xx, w23, acc[2][1]);
            PACK_DUP(xx, xr.w);
            FMA_F32X2(acc[3][0], xx, w01, acc[3][0]);
            FMA_F32X2(acc[3][1], xx, w23, acc[3][1]);
        }
    }
    size_t base = (size_t)blockIdx.z * NN * M;
#pragma unroll
    for (int i = 0; i < 4; i++) {
        float4 o;
        unsigned int u0, u1;
        asm("mov.b64 {%0, %1}, %2;" : "=r"(u0), "=r"(u1) : "l"(acc[i][0]));
        o.x = __uint_as_float(u0); o.y = __uint_as_float(u1);
        asm("mov.b64 {%0, %1}, %2;" : "=r"(u0), "=r"(u1) : "l"(acc[i][1]));
        o.z = __uint_as_float(u0); o.w = __uint_as_float(u1);
        *(float4*)&Cp[base + (size_t)(n0 + 4 * ty + i) * M + m0 + 4 * tx] = o;
    }
}

// ---------------- fused logit + windowed softmax + context -----------------
// one block per n (256 threads)
__global__ void logit_smax_ctx_kernel(const int* __restrict__ lengths,
                                      const float* __restrict__ b_enc,
                                      const float* __restrict__ conv_prev,
                                      const float* __restrict__ W_speed_att,
                                      const float* __restrict__ speed,
                                      const float* __restrict__ W_proj,
                                      const float* __restrict__ b_proj,
                                      float* __restrict__ out_ctx,
                                      int wctx) {
    int n = blockIdx.x;
    int a = threadIdx.x;           // 0..255
    int lane = a & 31, warp = a >> 5;
    __shared__ float red[8][TW];
    __shared__ float sm_lg[TW];

    float spd    = speed[n];
    float spk_a  = d_spkatt[n * ATT + a];
    float spda   = spd * W_speed_att[a];
    float wp     = W_proj[a];
    float be     = b_enc[a];

    float p[TW];
#pragma unroll
    for (int t = 0; t < TW; t++) {
        float v = be;
#pragma unroll
        for (int s = 0; s < SK_ATT; s++)
            v += d_C2p[(size_t)s * NB * TW * ATT + (size_t)(n * TW + t) * ATT + a];
        float e = v / (1.f + fabsf(v)) + spk_a + conv_prev[a * 31 + (15 - t)] + spda;
        p[t] = tanhf(e) * wp;
    }
#pragma unroll
    for (int off = 16; off > 0; off >>= 1)
#pragma unroll
        for (int t = 0; t < TW; t++)
            p[t] += __shfl_down_sync(0xffffffffu, p[t], off);
    if (lane == 0)
#pragma unroll
        for (int t = 0; t < TW; t++) red[warp][t] = p[t];
    __syncthreads();
    if (a < TW) {
        float tot = 0.f;
#pragma unroll
        for (int w = 0; w < 8; w++) tot += red[w][a];
        sm_lg[a] = tot + b_proj[0];
    }
    __syncthreads();

    // softmax over window (redundant per thread)
    int len = lengths[n];
    int len1 = (len > 1 ? len : 1) - 1;
    int hi = len1 < (TW - 1) ? len1 : (TW - 1);
    float m = -1e30f;
#pragma unroll
    for (int t = 0; t < TW; t++) { float l = sm_lg[t]; if (t <= hi && l > m) m = l; }
    float att[TW]; float s = 0.f;
#pragma unroll
    for (int t = 0; t < TW; t++) {
        float w = (t <= hi) ? __expf(sm_lg[t] - m) : 0.f;
        att[t] = w; s += w;
    }
    float inv = 1.f / fmaxf(s, 1e-12f);
#pragma unroll
    for (int t = 0; t < TW; t++) att[t] *= inv;

    // context over ENC (2 elems per thread)
#pragma unroll
    for (int it = 0; it < 2; it++) {
        int e = a + it * 256;
        float spv = d_sp[n * ENC + e];
        float acc = 0.f;
#pragma unroll
        for (int t = 0; t < TW; t++)
            acc += att[t] * (d_X2[((size_t)n * TW + t) * ENC + e] + spv);
        d_inlstm[n * INL + DEC + e]  = acc;     // [pre | ctx | spkr]
        d_deccat[n * CATL + HID + e] = acc;     // [h2 | ctx]
        if (wctx) out_ctx[n * ENC + e] = acc;
    }
}

// ---------------- LSTM gate (zero initial state => f gate dead) ------------
__global__ void lstm_gate_kernel(const float* __restrict__ gp,
                                 const float* __restrict__ bih,
                                 const float* __restrict__ bhh,
                                 float* __restrict__ hout,
                                 int out_stride, int S) {
    int idx = blockIdx.x * blockDim.x + threadIdx.x;   // n*HID + j
    if (idx >= NB * HID) return;
    int n = idx / HID, j = idx % HID;
    size_t row = (size_t)n * G4;
    float gi = bih[j]          + bhh[j];
    float gg = bih[2*HID + j]  + bhh[2*HID + j];
    float go = bih[3*HID + j]  + bhh[3*HID + j];
    for (int s = 0; s < S; s++) {
        size_t base = (size_t)s * NB * G4 + row;
        gi += gp[base + j];
        gg += gp[base + 2*HID + j];
        go += gp[base + 3*HID + j];
    }
    float si = 1.f / (1.f + __expf(-gi));
    float so = 1.f / (1.f + __expf(-go));
    float h = so * tanhf(si * tanhf(gg));
    hout[(size_t)n * out_stride + j] = h;
}

extern "C" void kernel_launch(void* const* d_in, const int* in_sizes, int n_in,
                              void* d_out, int out_size) {
    const float* input_enc   = (const float*)d_in[0];
    const float* input_dec   = (const float*)d_in[1];
    const float* spkr        = (const float*)d_in[2];
    const int*   lengths     = (const int*)  d_in[3];
    const float* speed       = (const float*)d_in[4];
    const float* W_enc       = (const float*)d_in[5];
    const float* b_enc       = (const float*)d_in[6];
    const float* W_spkr      = (const float*)d_in[7];
    const float* conv_prev   = (const float*)d_in[8];
    const float* W_speed_att = (const float*)d_in[9];
    const float* W_proj      = (const float*)d_in[10];
    const float* b_proj      = (const float*)d_in[11];
    const float* W_sp1       = (const float*)d_in[12];
    const float* b_sp1       = (const float*)d_in[13];
    const float* W_sp2       = (const float*)d_in[14];
    const float* b_sp2       = (const float*)d_in[15];
    const float* W_p1        = (const float*)d_in[16];
    const float* b_p1        = (const float*)d_in[17];
    const float* W_p2        = (const float*)d_in[18];
    const float* b_p2        = (const float*)d_in[19];
    const float* Wih0        = (const float*)d_in[20];
    const float* bih0        = (const float*)d_in[22];
    const float* bhh0        = (const float*)d_in[23];
    const float* Wih1        = (const float*)d_in[24];
    const float* bih1        = (const float*)d_in[26];
    const float* bhh1        = (const float*)d_in[27];
    const float* W_out       = (const float*)d_in[28];
    const float* b_out       = (const float*)d_in[29];

    float* out = (float*)d_out;
    int wctx = (out_size >= NB * OUTM + NB * ENC) ? 1 : 0;

    static float *p_xcat = nullptr, *p_s1, *p_p1, *p_sp, *p_spk, *p_X2,
                 *p_inl, *p_g0, *p_h1, *p_g1, *p_cat, *p_C2;
    if (!p_xcat) {
        cudaGetSymbolAddress((void**)&p_xcat, d_xcat);
        cudaGetSymbolAddress((void**)&p_s1,   d_s1);
        cudaGetSymbolAddress((void**)&p_p1,   d_p1);
        cudaGetSymbolAddress((void**)&p_sp,   d_sp);
        cudaGetSymbolAddress((void**)&p_spk,  d_spkatt);
        cudaGetSymbolAddress((void**)&p_X2,   d_X2);
        cudaGetSymbolAddress((void**)&p_inl,  d_inlstm);
        cudaGetSymbolAddress((void**)&p_g0,   d_g0p);
        cudaGetSymbolAddress((void**)&p_h1,   d_h1);
        cudaGetSymbolAddress((void**)&p_g1,   d_g1p);
        cudaGetSymbolAddress((void**)&p_cat,  d_deccat);
        cudaGetSymbolAddress((void**)&p_C2,   d_C2p);
    }

    int prep_threads = NB * XCATK + NB * DEC + NB * SPK + NB * TW * ENC;
    prep0_kernel<<<(prep_threads + 255) / 256, 256>>>(input_dec, spkr, speed,
                                                      W_sp1, b_sp1, input_enc);

    // spkatt: softsign(spkr @ W_spkr^T), K=64 M=256
    linW_kernel<<<dim3(ATT / 8, NB / 4), 256>>>(spkr, W_spkr, nullptr, p_spk,
                                                SPK, ATT, ATT, 3);
    // prenet layer 1: relu(xcat @ W_p1^T + b), K=144 M=512
    linW_kernel<<<dim3(512 / 8, NB / 4), 256>>>(p_xcat, W_p1, b_p1, p_p1,
                                                XCATK, 512, 512, 1);
    // speed proj layer 2: tanh(s1 @ W_sp2^T + b), K=256 M=512
    linW_kernel<<<dim3(ENC / 8, NB / 4), 256>>>(p_s1, W_sp2, b_sp2, p_sp,
                                                DEC, ENC, ENC, 2);

    // attention-energy GEMM on the 10-step window: [640,512]x[256,512]
    gemm64_kernel<<<dim3(ATT / 64, (NB * TW) / 64, SK_ATT), dim3(16, 16)>>>(
        p_X2, W_enc, p_C2, NB * TW, ATT, ENC);

    // prenet layer 2: relu(p1 @ W_p2^T + b) -> directly into inlstm[:,0:256]
    linW_kernel<<<dim3(DEC / 8, NB / 4), 256>>>(p_p1, W_p2, b_p2, p_inl,
                                                512, DEC, INL, 1);

    // fused logit + softmax + context (writes ctx into inlstm/deccat/out)
    logit_smax_ctx_kernel<<<NB, 256>>>(lengths, b_enc, conv_prev, W_speed_att,
                                       speed, W_proj, b_proj, out + NB * OUTM, wctx);

    // LSTM layer 0: [64,832] x [4096,832]
    gemm64_kernel<<<dim3(G4 / 64, 1, SK_L0), dim3(16, 16)>>>(p_inl, Wih0, p_g0, NB, G4, INL);
    lstm_gate_kernel<<<(NB * HID + 255) / 256, 256>>>(p_g0, bih0, bhh0, p_h1, HID, SK_L0);

    // LSTM layer 1: [64,1024] x [4096,1024]
    gemm64_kernel<<<dim3(G4 / 64, 1, SK_L1), dim3(16, 16)>>>(p_h1, Wih1, p_g1, NB, G4, HID);
    lstm_gate_kernel<<<(NB * HID + 255) / 256, 256>>>(p_g1, bih1, bhh1, p_cat, CATL, SK_L1);

    // output linear: [64,1536] x [160,1536] -> d_out[0:10240]
    linW_kernel<<<dim3(OUTM / 8, NB / 4), 256>>>(p_cat, W_out, b_out, out,
                                                 CATL, OUTM, OUTM, 0);
}

// round 12
// speedup vs baseline: 1.6986x; 1.0242x over previous
#include <cuda_runtime.h>
#include <math.h>

// ---------------- problem constants ----------------
#define NB     64      // batch
#define TT     2000
#define TW     10      // attention window (t in [0, 9])
#define ENC    512
#define ATT    256
#define DEC    256
#define SPK    64
#define OOUT   80
#define HID    1024    // 4*DEC
#define G4     4096    // 4*HID
#define INL    832     // ENC + DEC + SPK
#define CATL   1536    // HID + ENC
#define OUTM   160     // O*R
#define XCATK  144     // O + SPK
#define SK_ATT 4       // 512/4  = 128
#define SK_L0  13      // 832/13 = 64
#define SK_L1  8       // 1024/8 = 128

// packed fp32x2 helpers (sm_103a)
#define FMA_F32X2(d, a, b, c) \
    asm("fma.rn.f32x2 %0, %1, %2, %3;" : "=l"(d) : "l"(a), "l"(b), "l"(c))
#define PACK_DUP(d, f) \
    asm("mov.b64 %0, {%1, %1};" : "=l"(d) : "r"(__float_as_uint(f)))

// ---------------- scratch (device globals; no allocs allowed) ----------------
__device__ float d_xcat  [NB * XCATK];
__device__ float d_s1    [NB * DEC];
__device__ float d_p1    [NB * 512];
__device__ float d_sp    [NB * ENC];
__device__ float d_spkatt[NB * ATT];
__device__ float d_X2    [NB * TW * ENC];
__device__ float d_C2p   [SK_ATT * NB * TW * ATT];
__device__ float d_inlstm[NB * INL];
__device__ float d_g0p   [SK_L0 * NB * G4];
__device__ float d_h1    [NB * HID];
__device__ float d_g1p   [SK_L1 * NB * G4];
__device__ float d_deccat[NB * CATL];

// ---------------- kernel 1: gathers / tiny elementwise prep ----------------
// builds xcat, s1, X2 gather (float4), stages spkr into d_inlstm tail
__global__ void prep0_kernel(const float* __restrict__ input_dec,
                             const float* __restrict__ spkr,
                             const float* __restrict__ speed,
                             const float* __restrict__ W_sp1,
                             const float* __restrict__ b_sp1,
                             const float* __restrict__ input_enc) {
    int i = blockIdx.x * blockDim.x + threadIdx.x;
    const int N_XCAT = NB * XCATK;             // 9216
    const int N_S1   = NB * DEC;               // 16384
    const int N_SPK  = NB * SPK;               // 4096
    const int N_X24  = NB * TW * ENC / 4;      // 81920 float4s
    if (i < N_XCAT) {
        int n = i / XCATK, c = i % XCATK;
        d_xcat[i] = (c < OOUT) ? input_dec[n * OOUT + c] : spkr[n * SPK + (c - OOUT)];
        return;
    }
    i -= N_XCAT;
    if (i < N_S1) {
        int n = i / DEC, d = i % DEC;
        float v = speed[n] * W_sp1[d] + b_sp1[d];
        d_s1[i] = v > 0.f ? v : 0.f;
        return;
    }
    i -= N_S1;
    if (i < N_SPK) {
        int n = i / SPK, c = i % SPK;
        d_inlstm[n * INL + DEC + ENC + c] = spkr[i];
        return;
    }
    i -= N_SPK;
    if (i < N_X24) {
        const int E4 = ENC / 4;                 // 128 float4 per row
        int r = i / E4, k4 = i % E4;
        int n = r / TW, t = r % TW;
        ((float4*)d_X2)[i] =
            ((const float4*)input_enc)[((size_t)n * TT + t) * E4 + k4];
    }
}

// ---------------- warp-per-output linear body -------------------------------
// act: 0 none, 1 relu, 2 tanh, 3 softsign
__device__ __forceinline__ void lin_warp_body(const float* __restrict__ X,
                                              const float* __restrict__ W,
                                              const float* __restrict__ b,
                                              float* __restrict__ C,
                                              int K, int ldc, int act,
                                              int m, int n0, int lane) {
    const float* wrow = W + (size_t)m * K;
    float a0 = 0.f, a1 = 0.f, a2 = 0.f, a3 = 0.f;
    if ((K & 127) == 0) {
        const float* x0 = X + (size_t)(n0 + 0) * K;
        const float* x1 = X + (size_t)(n0 + 1) * K;
        const float* x2 = X + (size_t)(n0 + 2) * K;
        const float* x3 = X + (size_t)(n0 + 3) * K;
        for (int k = lane * 4; k < K; k += 128) {
            float4 wv = *(const float4*)(wrow + k);
            float4 v;
            v = *(const float4*)(x0 + k);
            a0 += v.x * wv.x + v.y * wv.y + v.z * wv.z + v.w * wv.w;
            v = *(const float4*)(x1 + k);
            a1 += v.x * wv.x + v.y * wv.y + v.z * wv.z + v.w * wv.w;
            v = *(const float4*)(x2 + k);
            a2 += v.x * wv.x + v.y * wv.y + v.z * wv.z + v.w * wv.w;
            v = *(const float4*)(x3 + k);
            a3 += v.x * wv.x + v.y * wv.y + v.z * wv.z + v.w * wv.w;
        }
    } else {
        for (int k = lane; k < K; k += 32) {
            float wv = wrow[k];
            a0 += X[(size_t)(n0 + 0) * K + k] * wv;
            a1 += X[(size_t)(n0 + 1) * K + k] * wv;
            a2 += X[(size_t)(n0 + 2) * K + k] * wv;
            a3 += X[(size_t)(n0 + 3) * K + k] * wv;
        }
    }
#pragma unroll
    for (int off = 16; off > 0; off >>= 1) {
        a0 += __shfl_down_sync(0xffffffffu, a0, off);
        a1 += __shfl_down_sync(0xffffffffu, a1, off);
        a2 += __shfl_down_sync(0xffffffffu, a2, off);
        a3 += __shfl_down_sync(0xffffffffu, a3, off);
    }
    if (lane == 0) {
        float bb = b ? b[m] : 0.f;
        float r[4] = {a0 + bb, a1 + bb, a2 + bb, a3 + bb};
#pragma unroll
        for (int i = 0; i < 4; i++) {
            float v = r[i];
            if (act == 1) v = v > 0.f ? v : 0.f;
            else if (act == 2) v = tanhf(v);
            else if (act == 3) v = v / (1.f + fabsf(v));
            C[(size_t)(n0 + i) * ldc + m] = v;
        }
    }
}

// generic single-linear kernel (prenet2, out)
__global__ void linW_kernel(const float* __restrict__ X,
                            const float* __restrict__ W,
                            const float* __restrict__ b,
                            float* __restrict__ C,
                            int K, int ldc, int act) {
    int warp = threadIdx.x >> 5, lane = threadIdx.x & 31;
    lin_warp_body(X, W, b, C, K, ldc, act,
                  blockIdx.x * 8 + warp, blockIdx.y * 4, lane);
}

// three independent small linears in ONE launch (segment dispatch on bx)
//  seg0: spkatt  = softsign(spkr @ W_spkr^T)        K=64  M=256 -> 32 x-blocks
//  seg1: p1      = relu(xcat @ W_p1^T + b_p1)       K=144 M=512 -> 64 x-blocks
//  seg2: sp      = tanh(s1 @ W_sp2^T + b_sp2)       K=256 M=512 -> 64 x-blocks
__global__ void multiLin_kernel(const float* __restrict__ spkr,
                                const float* __restrict__ W_spkr,
                                const float* __restrict__ W_p1,
                                const float* __restrict__ b_p1,
                                const float* __restrict__ W_sp2,
                                const float* __restrict__ b_sp2) {
    int warp = threadIdx.x >> 5, lane = threadIdx.x & 31;
    int bx = blockIdx.x;
    int n0 = blockIdx.y * 4;
    if (bx < 32) {
        lin_warp_body(spkr, W_spkr, nullptr, d_spkatt, SPK, ATT, 3,
                      bx * 8 + warp, n0, lane);
    } else if (bx < 96) {
        lin_warp_body(d_xcat, W_p1, b_p1, d_p1, XCATK, 512, 1,
                      (bx - 32) * 8 + warp, n0, lane);
    } else {
        lin_warp_body(d_s1, W_sp2, b_sp2, d_sp, DEC, ENC, 2,
                      (bx - 96) * 8 + warp, n0, lane);
    }
}

// ---------------- big GEMM (split-K partials, packed f32x2 math) -----------
// Cp[s][n,m] = sum_{k in split s} X[n,k]*W[m,k]
__global__ void gemm64_kernel(const float* __restrict__ X,
                              const float* __restrict__ W,
                              float* __restrict__ Cp,
                              int NN, int M, int K) {
    __shared__ float Xs[16][68];
    __shared__ float Ws[16][68];
    int S  = gridDim.z;
    int nk = K / S;
    int ks0 = nk * blockIdx.z;
    int m0 = blockIdx.x * 64;
    int n0 = blockIdx.y * 64;
    int tx = threadIdx.x, ty = threadIdx.y;
    int tid = ty * 16 + tx;
    int lr = tid >> 2;            // 0..63
    int lk = (tid & 3) * 4;       // 0,4,8,12
    const float* Xp = X + (size_t)(n0 + lr) * K + ks0 + lk;
    const float* Wp = W + (size_t)(m0 + lr) * K + ks0 + lk;

    unsigned long long acc[4][2];
#pragma unroll
    for (int i = 0; i < 4; i++) { acc[i][0] = 0ull; acc[i][1] = 0ull; }

    for (int kt = 0; kt < nk; kt += 16) {
        float4 xv = *(const float4*)(Xp + kt);
        float4 wv = *(const float4*)(Wp + kt);
        __syncthreads();
        Xs[lk + 0][lr] = xv.x; Xs[lk + 1][lr] = xv.y;
        Xs[lk + 2][lr] = xv.z; Xs[lk + 3][lr] = xv.w;
        Ws[lk + 0][lr] = wv.x; Ws[lk + 1][lr] = wv.y;
        Ws[lk + 2][lr] = wv.z; Ws[lk + 3][lr] = wv.w;
        __syncthreads();
#pragma unroll
        for (int k = 0; k < 16; k++) {
            float4 xr = *(const float4*)&Xs[k][4 * ty];
            unsigned long long w01 = *(const unsigned long long*)&Ws[k][4 * tx];
            unsigned long long w23 = *(const unsigned long long*)&Ws[k][4 * tx + 2];
            unsigned long long xx;
            PACK_DUP(xx, xr.x);
            FMA_F32X2(acc[0][0], xx, w01, acc[0][0]);
            FMA_F32X2(acc[0][1], xx, w23, acc[0][1]);
            PACK_DUP(xx, xr.y);
            FMA_F32X2(acc[1][0], xx, w01, acc[1][0]);
            FMA_F32X2(acc[1][1], xx, w23, acc[1][1]);
            PACK_DUP(xx, xr.z);
            FMA_F32X2(acc[2][0], xx, w01, acc[2][0]);
            FMA_F32X2(acc[2][1], xx, w23, acc[2][1]);
            PACK_DUP(xx, xr.w);
            FMA_F32X2(acc[3][0], xx, w01, acc[3][0]);
            FMA_F32X2(acc[3][1], xx, w23, acc[3][1]);
        }
    }
    size_t base = (size_t)blockIdx.z * NN * M;
#pragma unroll
    for (int i = 0; i < 4; i++) {
        float4 o;
        unsigned int u0, u1;
        asm("mov.b64 {%0, %1}, %2;" : "=r"(u0), "=r"(u1) : "l"(acc[i][0]));
        o.x = __uint_as_float(u0); o.y = __uint_as_float(u1);
        asm("mov.b64 {%0, %1}, %2;" : "=r"(u0), "=r"(u1) : "l"(acc[i][1]));
        o.z = __uint_as_float(u0); o.w = __uint_as_float(u1);
        *(float4*)&Cp[base + (size_t)(n0 + 4 * ty + i) * M + m0 + 4 * tx] = o;
    }
}

// ---------------- fused logit + windowed softmax + context -----------------
__global__ void logit_smax_ctx_kernel(const int* __restrict__ lengths,
                                      const float* __restrict__ b_enc,
                                      const float* __restrict__ conv_prev,
                                      const float* __restrict__ W_speed_att,
                                      const float* __restrict__ speed,
                                      const float* __restrict__ W_proj,
                                      const float* __restrict__ b_proj,
                                      float* __restrict__ out_ctx,
                                      int wctx) {
    int n = blockIdx.x;
    int a = threadIdx.x;           // 0..255
    int lane = a & 31, warp = a >> 5;
    __shared__ float red[8][TW];
    __shared__ float sm_lg[TW];

    float spd    = speed[n];
    float spk_a  = d_spkatt[n * ATT + a];
    float spda   = spd * W_speed_att[a];
    float wp     = W_proj[a];
    float be     = b_enc[a];

    float p[TW];
#pragma unroll
    for (int t = 0; t < TW; t++) {
        float v = be;
#pragma unroll
        for (int s = 0; s < SK_ATT; s++)
            v += d_C2p[(size_t)s * NB * TW * ATT + (size_t)(n * TW + t) * ATT + a];
        float e = v / (1.f + fabsf(v)) + spk_a + conv_prev[a * 31 + (15 - t)] + spda;
        p[t] = tanhf(e) * wp;
    }
#pragma unroll
    for (int off = 16; off > 0; off >>= 1)
#pragma unroll
        for (int t = 0; t < TW; t++)
            p[t] += __shfl_down_sync(0xffffffffu, p[t], off);
    if (lane == 0)
#pragma unroll
        for (int t = 0; t < TW; t++) red[warp][t] = p[t];
    __syncthreads();
    if (a < TW) {
        float tot = 0.f;
#pragma unroll
        for (int w = 0; w < 8; w++) tot += red[w][a];
        sm_lg[a] = tot + b_proj[0];
    }
    __syncthreads();

    int len = lengths[n];
    int len1 = (len > 1 ? len : 1) - 1;
    int hi = len1 < (TW - 1) ? len1 : (TW - 1);
    float m = -1e30f;
#pragma unroll
    for (int t = 0; t < TW; t++) { float l = sm_lg[t]; if (t <= hi && l > m) m = l; }
    float att[TW]; float s = 0.f;
#pragma unroll
    for (int t = 0; t < TW; t++) {
        float w = (t <= hi) ? __expf(sm_lg[t] - m) : 0.f;
        att[t] = w; s += w;
    }
    float inv = 1.f / fmaxf(s, 1e-12f);
#pragma unroll
    for (int t = 0; t < TW; t++) att[t] *= inv;

#pragma unroll
    for (int it = 0; it < 2; it++) {
        int e = a + it * 256;
        float spv = d_sp[n * ENC + e];
        float acc = 0.f;
#pragma unroll
        for (int t = 0; t < TW; t++)
            acc += att[t] * (d_X2[((size_t)n * TW + t) * ENC + e] + spv);
        d_inlstm[n * INL + DEC + e]  = acc;     // [pre | ctx | spkr]
        d_deccat[n * CATL + HID + e] = acc;     // [h2 | ctx]
        if (wctx) out_ctx[n * ENC + e] = acc;
    }
}

// ---------------- LSTM gate (zero initial state => f gate dead) ------------
__global__ void lstm_gate_kernel(const float* __restrict__ gp,
                                 const float* __restrict__ bih,
                                 const float* __restrict__ bhh,
                                 float* __restrict__ hout,
                                 int out_stride, int S) {
    int idx = blockIdx.x * blockDim.x + threadIdx.x;   // n*HID + j
    if (idx >= NB * HID) return;
    int n = idx / HID, j = idx % HID;
    size_t row = (size_t)n * G4;
    float gi = bih[j]          + bhh[j];
    float gg = bih[2*HID + j]  + bhh[2*HID + j];
    float go = bih[3*HID + j]  + bhh[3*HID + j];
    for (int s = 0; s < S; s++) {
        size_t base = (size_t)s * NB * G4 + row;
        gi += gp[base + j];
        gg += gp[base + 2*HID + j];
        go += gp[base + 3*HID + j];
    }
    float si = 1.f / (1.f + __expf(-gi));
    float so = 1.f / (1.f + __expf(-go));
    float h = so * tanhf(si * tanhf(gg));
    hout[(size_t)n * out_stride + j] = h;
}

extern "C" void kernel_launch(void* const* d_in, const int* in_sizes, int n_in,
                              void* d_out, int out_size) {
    const float* input_enc   = (const float*)d_in[0];
    const float* input_dec   = (const float*)d_in[1];
    const float* spkr        = (const float*)d_in[2];
    const int*   lengths     = (const int*)  d_in[3];
    const float* speed       = (const float*)d_in[4];
    const float* W_enc       = (const float*)d_in[5];
    const float* b_enc       = (const float*)d_in[6];
    const float* W_spkr      = (const float*)d_in[7];
    const float* conv_prev   = (const float*)d_in[8];
    const float* W_speed_att = (const float*)d_in[9];
    const float* W_proj      = (const float*)d_in[10];
    const float* b_proj      = (const float*)d_in[11];
    const float* W_sp1       = (const float*)d_in[12];
    const float* b_sp1       = (const float*)d_in[13];
    const float* W_sp2       = (const float*)d_in[14];
    const float* b_sp2       = (const float*)d_in[15];
    const float* W_p1        = (const float*)d_in[16];
    const float* b_p1        = (const float*)d_in[17];
    const float* W_p2        = (const float*)d_in[18];
    const float* b_p2        = (const float*)d_in[19];
    const float* Wih0        = (const float*)d_in[20];
    const float* bih0        = (const float*)d_in[22];
    const float* bhh0        = (const float*)d_in[23];
    const float* Wih1        = (const float*)d_in[24];
    const float* bih1        = (const float*)d_in[26];
    const float* bhh1        = (const float*)d_in[27];
    const float* W_out       = (const float*)d_in[28];
    const float* b_out       = (const float*)d_in[29];

    float* out = (float*)d_out;
    int wctx = (out_size >= NB * OUTM + NB * ENC) ? 1 : 0;

    // one-time setup (first call = correctness run, before graph capture):
    // resolve scratch addresses; create side stream + events for the forked
    // branch of the graph. All are created outside capture and reused.
    static float *p_xcat = nullptr, *p_s1, *p_p1, *p_sp, *p_spk, *p_X2,
                 *p_inl, *p_g0, *p_h1, *p_g1, *p_cat, *p_C2;
    static cudaStream_t s1;
    static cudaEvent_t evFork, evJoin;
    if (!p_xcat) {
        cudaGetSymbolAddress((void**)&p_xcat, d_xcat);
        cudaGetSymbolAddress((void**)&p_s1,   d_s1);
        cudaGetSymbolAddress((void**)&p_p1,   d_p1);
        cudaGetSymbolAddress((void**)&p_sp,   d_sp);
        cudaGetSymbolAddress((void**)&p_spk,  d_spkatt);
        cudaGetSymbolAddress((void**)&p_X2,   d_X2);
        cudaGetSymbolAddress((void**)&p_inl,  d_inlstm);
        cudaGetSymbolAddress((void**)&p_g0,   d_g0p);
        cudaGetSymbolAddress((void**)&p_h1,   d_h1);
        cudaGetSymbolAddress((void**)&p_g1,   d_g1p);
        cudaGetSymbolAddress((void**)&p_cat,  d_deccat);
        cudaGetSymbolAddress((void**)&p_C2,   d_C2p);
        cudaStreamCreateWithFlags(&s1, cudaStreamNonBlocking);
        cudaEventCreateWithFlags(&evFork, cudaEventDisableTiming);
        cudaEventCreateWithFlags(&evJoin, cudaEventDisableTiming);
    }

    int prep_threads = NB * XCATK + NB * DEC + NB * SPK + NB * TW * ENC / 4;
    prep0_kernel<<<(prep_threads + 255) / 256, 256>>>(input_dec, spkr, speed,
                                                      W_sp1, b_sp1, input_enc);

    // ---- fork: small-linear branch on s1, attention GEMM on main stream ----
    cudaEventRecord(evFork, 0);
    cudaStreamWaitEvent(s1, evFork, 0);

    // s1: spkatt + prenet1 + speedproj2 in ONE launch, then prenet2
    multiLin_kernel<<<dim3(160, NB / 4), 256, 0, s1>>>(spkr, W_spkr,
                                                       W_p1, b_p1, W_sp2, b_sp2);
    linW_kernel<<<dim3(DEC / 8, NB / 4), 256, 0, s1>>>(p_p1, W_p2, b_p2, p_inl,
                                                       512, INL, 1);
    cudaEventRecord(evJoin, s1);

    // main: attention-energy GEMM on the 10-step window [640,512]x[256,512]
    gemm64_kernel<<<dim3(ATT / 64, (NB * TW) / 64, SK_ATT), dim3(16, 16)>>>(
        p_X2, W_enc, p_C2, NB * TW, ATT, ENC);

    // ---- join ----
    cudaStreamWaitEvent(0, evJoin, 0);

    // fused logit + softmax + context (writes ctx into inlstm/deccat/out)
    logit_smax_ctx_kernel<<<NB, 256>>>(lengths, b_enc, conv_prev, W_speed_att,
                                       speed, W_proj, b_proj, out + NB * OUTM, wctx);

    // LSTM layer 0: [64,832] x [4096,832]
    gemm64_kernel<<<dim3(G4 / 64, 1, SK_L0), dim3(16, 16)>>>(p_inl, Wih0, p_g0, NB, G4, INL);
    lstm_gate_kernel<<<(NB * HID + 255) / 256, 256>>>(p_g0, bih0, bhh0, p_h1, HID, SK_L0);

    // LSTM layer 1: [64,1024] x [4096,1024]
    gemm64_kernel<<<dim3(G4 / 64, 1, SK_L1), dim3(16, 16)>>>(p_h1, Wih1, p_g1, NB, G4, HID);
    lstm_gate_kernel<<<(NB * HID + 255) / 256, 256>>>(p_g1, bih1, bhh1, p_cat, CATL, SK_L1);

    // output linear: [64,1536] x [160,1536] -> d_out[0:10240]
    linW_kernel<<<dim3(OUTM / 8, NB / 4), 256>>>(p_cat, W_out, b_out, out,
                                                 CATL, OUTM, 0);
}

// round 15
// speedup vs baseline: 1.8233x; 1.0734x over previous
#include <cuda_runtime.h>
#include <math.h>

// ---------------- problem constants ----------------
#define NB     64      // batch
#define TT     2000
#define TW     10      // attention window (t in [0, 9])
#define ENC    512
#define ATT    256
#define DEC    256
#define SPK    64
#define OOUT   80
#define HID    1024    // 4*DEC
#define G4     4096    // 4*HID
#define INL    832     // ENC + DEC + SPK
#define CATL   1536    // HID + ENC
#define OUTM   160     // O*R
#define XCATK  144     // O + SPK
#define SK_ATT 8       // 512/8  = 64  -> 4 k-tiles, grid 320
#define SK_L0  13      // 832/13 = 64  -> 4 k-tiles, grid 832
#define SK_L1  16      // 1024/16= 64  -> 4 k-tiles, grid 1024

// packed fp32x2 helpers (sm_103a)
#define FMA_F32X2(d, a, b, c) \
    asm("fma.rn.f32x2 %0, %1, %2, %3;" : "=l"(d) : "l"(a), "l"(b), "l"(c))
#define PACK_DUP(d, f) \
    asm("mov.b64 %0, {%1, %1};" : "=l"(d) : "r"(__float_as_uint(f)))

// ---------------- scratch (device globals; no allocs allowed) ----------------
__device__ float d_xcat  [NB * XCATK];
__device__ float d_s1    [NB * DEC];
__device__ float d_p1    [NB * 512];
__device__ float d_sp    [NB * ENC];
__device__ float d_spkatt[NB * ATT];
__device__ float d_X2    [NB * TW * ENC];
__device__ float d_C2p   [SK_ATT * NB * TW * ATT];
__device__ float d_inlstm[NB * INL];
__device__ float d_g0p   [SK_L0 * NB * G4];
__device__ float d_h1    [NB * HID];
__device__ float d_g1p   [SK_L1 * NB * G4];
__device__ float d_deccat[NB * CATL];

// ---------------- kernel 1: gathers / tiny elementwise prep ----------------
__global__ void prep0_kernel(const float* __restrict__ input_dec,
                             const float* __restrict__ spkr,
                             const float* __restrict__ speed,
                             const float* __restrict__ W_sp1,
                             const float* __restrict__ b_sp1,
                             const float* __restrict__ input_enc) {
    int i = blockIdx.x * blockDim.x + threadIdx.x;
    const int N_XCAT = NB * XCATK;             // 9216
    const int N_S1   = NB * DEC;               // 16384
    const int N_SPK  = NB * SPK;               // 4096
    const int N_X24  = NB * TW * ENC / 4;      // 81920 float4s
    if (i < N_XCAT) {
        int n = i / XCATK, c = i % XCATK;
        d_xcat[i] = (c < OOUT) ? input_dec[n * OOUT + c] : spkr[n * SPK + (c - OOUT)];
        return;
    }
    i -= N_XCAT;
    if (i < N_S1) {
        int n = i / DEC, d = i % DEC;
        float v = speed[n] * W_sp1[d] + b_sp1[d];
        d_s1[i] = v > 0.f ? v : 0.f;
        return;
    }
    i -= N_S1;
    if (i < N_SPK) {
        int n = i / SPK, c = i % SPK;
        d_inlstm[n * INL + DEC + ENC + c] = spkr[i];
        return;
    }
    i -= N_SPK;
    if (i < N_X24) {
        const int E4 = ENC / 4;
        int r = i / E4, k4 = i % E4;
        int n = r / TW, t = r % TW;
        ((float4*)d_X2)[i] =
            ((const float4*)input_enc)[((size_t)n * TT + t) * E4 + k4];
    }
}

// ---------------- warp-per-output linear body -------------------------------
__device__ __forceinline__ void lin_warp_body(const float* __restrict__ X,
                                              const float* __restrict__ W,
                                              const float* __restrict__ b,
                                              float* __restrict__ C,
                                              int K, int ldc, int act,
                                              int m, int n0, int lane) {
    const float* wrow = W + (size_t)m * K;
    float a0 = 0.f, a1 = 0.f, a2 = 0.f, a3 = 0.f;
    if ((K & 127) == 0) {
        const float* x0 = X + (size_t)(n0 + 0) * K;
        const float* x1 = X + (size_t)(n0 + 1) * K;
        const float* x2 = X + (size_t)(n0 + 2) * K;
        const float* x3 = X + (size_t)(n0 + 3) * K;
        for (int k = lane * 4; k < K; k += 128) {
            float4 wv = *(const float4*)(wrow + k);
            float4 v;
            v = *(const float4*)(x0 + k);
            a0 += v.x * wv.x + v.y * wv.y + v.z * wv.z + v.w * wv.w;
            v = *(const float4*)(x1 + k);
            a1 += v.x * wv.x + v.y * wv.y + v.z * wv.z + v.w * wv.w;
            v = *(const float4*)(x2 + k);
            a2 += v.x * wv.x + v.y * wv.y + v.z * wv.z + v.w * wv.w;
            v = *(const float4*)(x3 + k);
            a3 += v.x * wv.x + v.y * wv.y + v.z * wv.z + v.w * wv.w;
        }
    } else {
        for (int k = lane; k < K; k += 32) {
            float wv = wrow[k];
            a0 += X[(size_t)(n0 + 0) * K + k] * wv;
            a1 += X[(size_t)(n0 + 1) * K + k] * wv;
            a2 += X[(size_t)(n0 + 2) * K + k] * wv;
            a3 += X[(size_t)(n0 + 3) * K + k] * wv;
        }
    }
#pragma unroll
    for (int off = 16; off > 0; off >>= 1) {
        a0 += __shfl_down_sync(0xffffffffu, a0, off);
        a1 += __shfl_down_sync(0xffffffffu, a1, off);
        a2 += __shfl_down_sync(0xffffffffu, a2, off);
        a3 += __shfl_down_sync(0xffffffffu, a3, off);
    }
    if (lane == 0) {
        float bb = b ? b[m] : 0.f;
        float r[4] = {a0 + bb, a1 + bb, a2 + bb, a3 + bb};
#pragma unroll
        for (int i = 0; i < 4; i++) {
            float v = r[i];
            if (act == 1) v = v > 0.f ? v : 0.f;
            else if (act == 2) v = tanhf(v);
            else if (act == 3) v = v / (1.f + fabsf(v));
            C[(size_t)(n0 + i) * ldc + m] = v;
        }
    }
}

__global__ void linW_kernel(const float* __restrict__ X,
                            const float* __restrict__ W,
                            const float* __restrict__ b,
                            float* __restrict__ C,
                            int K, int ldc, int act) {
    int warp = threadIdx.x >> 5, lane = threadIdx.x & 31;
    lin_warp_body(X, W, b, C, K, ldc, act,
                  blockIdx.x * 8 + warp, blockIdx.y * 4, lane);
}

// three independent small linears in ONE launch (segment dispatch on bx)
__global__ void multiLin_kernel(const float* __restrict__ spkr,
                                const float* __restrict__ W_spkr,
                                const float* __restrict__ W_p1,
                                const float* __restrict__ b_p1,
                                const float* __restrict__ W_sp2,
                                const float* __restrict__ b_sp2) {
    int warp = threadIdx.x >> 5, lane = threadIdx.x & 31;
    int bx = blockIdx.x;
    int n0 = blockIdx.y * 4;
    if (bx < 32) {
        lin_warp_body(spkr, W_spkr, nullptr, d_spkatt, SPK, ATT, 3,
                      bx * 8 + warp, n0, lane);
    } else if (bx < 96) {
        lin_warp_body(d_xcat, W_p1, b_p1, d_p1, XCATK, 512, 1,
                      (bx - 32) * 8 + warp, n0, lane);
    } else {
        lin_warp_body(d_s1, W_sp2, b_sp2, d_sp, DEC, ENC, 2,
                      (bx - 96) * 8 + warp, n0, lane);
    }
}

// ---------------- big GEMM: double-buffered smem + register prefetch -------
// Cp[s][n,m] = sum_{k in split s} X[n,k]*W[m,k]; one __syncthreads per tile.
__global__ void gemm64_kernel(const float* __restrict__ X,
                              const float* __restrict__ W,
                              float* __restrict__ Cp,
                              int NN, int M, int K) {
    __shared__ float Xs[2][16][68];
    __shared__ float Ws[2][16][68];
    int S  = gridDim.z;
    int nk = K / S;
    int ks0 = nk * blockIdx.z;
    int m0 = blockIdx.x * 64;
    int n0 = blockIdx.y * 64;
    int tx = threadIdx.x, ty = threadIdx.y;
    int tid = ty * 16 + tx;
    int lr = tid >> 2;            // 0..63
    int lk = (tid & 3) * 4;       // 0,4,8,12
    const float* Xp = X + (size_t)(n0 + lr) * K + ks0 + lk;
    const float* Wp = W + (size_t)(m0 + lr) * K + ks0 + lk;

    unsigned long long acc[4][2];
#pragma unroll
    for (int i = 0; i < 4; i++) { acc[i][0] = 0ull; acc[i][1] = 0ull; }

    // prologue: tile 0 -> buffer 0
    float4 xv = *(const float4*)(Xp);
    float4 wv = *(const float4*)(Wp);
    Xs[0][lk + 0][lr] = xv.x; Xs[0][lk + 1][lr] = xv.y;
    Xs[0][lk + 2][lr] = xv.z; Xs[0][lk + 3][lr] = xv.w;
    Ws[0][lk + 0][lr] = wv.x; Ws[0][lk + 1][lr] = wv.y;
    Ws[0][lk + 2][lr] = wv.z; Ws[0][lk + 3][lr] = wv.w;
    __syncthreads();

    int nt = nk >> 4;
    for (int it = 0; it < nt; it++) {
        int buf = it & 1;
        int more = (it + 1 < nt);
        if (more) {                              // prefetch next tile (hidden by compute)
            xv = *(const float4*)(Xp + (it + 1) * 16);
            wv = *(const float4*)(Wp + (it + 1) * 16);
        }
#pragma unroll
        for (int k = 0; k < 16; k++) {
            float4 xr = *(const float4*)&Xs[buf][k][4 * ty];
            unsigned long long w01 = *(const unsigned long long*)&Ws[buf][k][4 * tx];
            unsigned long long w23 = *(const unsigned long long*)&Ws[buf][k][4 * tx + 2];
            unsigned long long xx;
            PACK_DUP(xx, xr.x);
            FMA_F32X2(acc[0][0], xx, w01, acc[0][0]);
            FMA_F32X2(acc[0][1], xx, w23, acc[0][1]);
            PACK_DUP(xx, xr.y);
            FMA_F32X2(acc[1][0], xx, w01, acc[1][0]);
            FMA_F32X2(acc[1][1], xx, w23, acc[1][1]);
            PACK_DUP(xx, xr.z);
            FMA_F32X2(acc[2][0], xx, w01, acc[2][0]);
            FMA_F32X2(acc[2][1], xx, w23, acc[2][1]);
            PACK_DUP(xx, xr.w);
            FMA_F32X2(acc[3][0], xx, w01, acc[3][0]);
            FMA_F32X2(acc[3][1], xx, w23, acc[3][1]);
        }
        if (more) {                              // stash into the idle buffer
            int nb = buf ^ 1;
            Xs[nb][lk + 0][lr] = xv.x; Xs[nb][lk + 1][lr] = xv.y;
            Xs[nb][lk + 2][lr] = xv.z; Xs[nb][lk + 3][lr] = xv.w;
            Ws[nb][lk + 0][lr] = wv.x; Ws[nb][lk + 1][lr] = wv.y;
            Ws[nb][lk + 2][lr] = wv.z; Ws[nb][lk + 3][lr] = wv.w;
            __syncthreads();
        }
    }

    size_t base = (size_t)blockIdx.z * NN * M;
#pragma unroll
    for (int i = 0; i < 4; i++) {
        float4 o;
        unsigned int u0, u1;
        asm("mov.b64 {%0, %1}, %2;" : "=r"(u0), "=r"(u1) : "l"(acc[i][0]));
        o.x = __uint_as_float(u0); o.y = __uint_as_float(u1);
        asm("mov.b64 {%0, %1}, %2;" : "=r"(u0), "=r"(u1) : "l"(acc[i][1]));
        o.z = __uint_as_float(u0); o.w = __uint_as_float(u1);
        *(float4*)&Cp[base + (size_t)(n0 + 4 * ty + i) * M + m0 + 4 * tx] = o;
    }
}

// ---------------- fused logit + windowed softmax + context -----------------
__global__ void logit_smax_ctx_kernel(const int* __restrict__ lengths,
                                      const float* __restrict__ b_enc,
                                      const float* __restrict__ conv_prev,
                                      const float* __restrict__ W_speed_att,
                                      const float* __restrict__ speed,
                                      const float* __restrict__ W_proj,
                                      const float* __restrict__ b_proj,
                                      float* __restrict__ out_ctx,
                                      int wctx) {
    int n = blockIdx.x;
    int a = threadIdx.x;           // 0..255
    int lane = a & 31, warp = a >> 5;
    __shared__ float red[8][TW];
    __shared__ float sm_lg[TW];

    float spd    = speed[n];
    float spk_a  = d_spkatt[n * ATT + a];
    float spda   = spd * W_speed_att[a];
    float wp     = W_proj[a];
    float be     = b_enc[a];

    float p[TW];
#pragma unroll
    for (int t = 0; t < TW; t++) {
        float v = be;
#pragma unroll
        for (int s = 0; s < SK_ATT; s++)
            v += d_C2p[(size_t)s * NB * TW * ATT + (size_t)(n * TW + t) * ATT + a];
        float e = v / (1.f + fabsf(v)) + spk_a + conv_prev[a * 31 + (15 - t)] + spda;
        p[t] = tanhf(e) * wp;
    }
#pragma unroll
    for (int off = 16; off > 0; off >>= 1)
#pragma unroll
        for (int t = 0; t < TW; t++)
            p[t] += __shfl_down_sync(0xffffffffu, p[t], off);
    if (lane == 0)
#pragma unroll
        for (int t = 0; t < TW; t++) red[warp][t] = p[t];
    __syncthreads();
    if (a < TW) {
        float tot = 0.f;
#pragma unroll
        for (int w = 0; w < 8; w++) tot += red[w][a];
        sm_lg[a] = tot + b_proj[0];
    }
    __syncthreads();

    int len = lengths[n];
    int len1 = (len > 1 ? len : 1) - 1;
    int hi = len1 < (TW - 1) ? len1 : (TW - 1);
    float m = -1e30f;
#pragma unroll
    for (int t = 0; t < TW; t++) { float l = sm_lg[t]; if (t <= hi && l > m) m = l; }
    float att[TW]; float s = 0.f;
#pragma unroll
    for (int t = 0; t < TW; t++) {
        float w = (t <= hi) ? __expf(sm_lg[t] - m) : 0.f;
        att[t] = w; s += w;
    }
    float inv = 1.f / fmaxf(s, 1e-12f);
#pragma unroll
    for (int t = 0; t < TW; t++) att[t] *= inv;

#pragma unroll
    for (int it = 0; it < 2; it++) {
        int e = a + it * 256;
        float spv = d_sp[n * ENC + e];
        float acc = 0.f;
#pragma unroll
        for (int t = 0; t < TW; t++)
            acc += att[t] * (d_X2[((size_t)n * TW + t) * ENC + e] + spv);
        d_inlstm[n * INL + DEC + e]  = acc;     // [pre | ctx | spkr]
        d_deccat[n * CATL + HID + e] = acc;     // [h2 | ctx]
        if (wctx) out_ctx[n * ENC + e] = acc;
    }
}

// ---------------- LSTM gate (zero initial state => f gate dead) ------------
__global__ void lstm_gate_kernel(const float* __restrict__ gp,
                                 const float* __restrict__ bih,
                                 const float* __restrict__ bhh,
                                 float* __restrict__ hout,
                                 int out_stride, int S) {
    int idx = blockIdx.x * blockDim.x + threadIdx.x;   // n*HID + j
    if (idx >= NB * HID) return;
    int n = idx / HID, j = idx % HID;
    size_t row = (size_t)n * G4;
    float gi = bih[j]          + bhh[j];
    float gg = bih[2*HID + j]  + bhh[2*HID + j];
    float go = bih[3*HID + j]  + bhh[3*HID + j];
    for (int s = 0; s < S; s++) {
        size_t base = (size_t)s * NB * G4 + row;
        gi += gp[base + j];
        gg += gp[base + 2*HID + j];
        go += gp[base + 3*HID + j];
    }
    float si = 1.f / (1.f + __expf(-gi));
    float so = 1.f / (1.f + __expf(-go));
    float h = so * tanhf(si * tanhf(gg));
    hout[(size_t)n * out_stride + j] = h;
}

extern "C" void kernel_launch(void* const* d_in, const int* in_sizes, int n_in,
                              void* d_out, int out_size) {
    const float* input_enc   = (const float*)d_in[0];
    const float* input_dec   = (const float*)d_in[1];
    const float* spkr        = (const float*)d_in[2];
    const int*   lengths     = (const int*)  d_in[3];
    const float* speed       = (const float*)d_in[4];
    const float* W_enc       = (const float*)d_in[5];
    const float* b_enc       = (const float*)d_in[6];
    const float* W_spkr      = (const float*)d_in[7];
    const float* conv_prev   = (const float*)d_in[8];
    const float* W_speed_att = (const float*)d_in[9];
    const float* W_proj      = (const float*)d_in[10];
    const float* b_proj      = (const float*)d_in[11];
    const float* W_sp1       = (const float*)d_in[12];
    const float* b_sp1       = (const float*)d_in[13];
    const float* W_sp2       = (const float*)d_in[14];
    const float* b_sp2       = (const float*)d_in[15];
    const float* W_p1        = (const float*)d_in[16];
    const float* b_p1        = (const float*)d_in[17];
    const float* W_p2        = (const float*)d_in[18];
    const float* b_p2        = (const float*)d_in[19];
    const float* Wih0        = (const float*)d_in[20];
    const float* bih0        = (const float*)d_in[22];
    const float* bhh0        = (const float*)d_in[23];
    const float* Wih1        = (const float*)d_in[24];
    const float* bih1        = (const float*)d_in[26];
    const float* bhh1        = (const float*)d_in[27];
    const float* W_out       = (const float*)d_in[28];
    const float* b_out       = (const float*)d_in[29];

    float* out = (float*)d_out;
    int wctx = (out_size >= NB * OUTM + NB * ENC) ? 1 : 0;

    static float *p_xcat = nullptr, *p_s1, *p_p1, *p_sp, *p_spk, *p_X2,
                 *p_inl, *p_g0, *p_h1, *p_g1, *p_cat, *p_C2;
    static cudaStream_t s1;
    static cudaEvent_t evFork, evJoin;
    if (!p_xcat) {
        cudaGetSymbolAddress((void**)&p_xcat, d_xcat);
        cudaGetSymbolAddress((void**)&p_s1,   d_s1);
        cudaGetSymbolAddress((void**)&p_p1,   d_p1);
        cudaGetSymbolAddress((void**)&p_sp,   d_sp);
        cudaGetSymbolAddress((void**)&p_spk,  d_spkatt);
        cudaGetSymbolAddress((void**)&p_X2,   d_X2);
        cudaGetSymbolAddress((void**)&p_inl,  d_inlstm);
        cudaGetSymbolAddress((void**)&p_g0,   d_g0p);
        cudaGetSymbolAddress((void**)&p_h1,   d_h1);
        cudaGetSymbolAddress((void**)&p_g1,   d_g1p);
        cudaGetSymbolAddress((void**)&p_cat,  d_deccat);
        cudaGetSymbolAddress((void**)&p_C2,   d_C2p);
        cudaStreamCreateWithFlags(&s1, cudaStreamNonBlocking);
        cudaEventCreateWithFlags(&evFork, cudaEventDisableTiming);
        cudaEventCreateWithFlags(&evJoin, cudaEventDisableTiming);
    }

    int prep_threads = NB * XCATK + NB * DEC + NB * SPK + NB * TW * ENC / 4;
    prep0_kernel<<<(prep_threads + 255) / 256, 256>>>(input_dec, spkr, speed,
                                                      W_sp1, b_sp1, input_enc);

    // ---- fork: small-linear branch on s1, attention GEMM on main stream ----
    cudaEventRecord(evFork, 0);
    cudaStreamWaitEvent(s1, evFork, 0);

    multiLin_kernel<<<dim3(160, NB / 4), 256, 0, s1>>>(spkr, W_spkr,
                                                       W_p1, b_p1, W_sp2, b_sp2);
    linW_kernel<<<dim3(DEC / 8, NB / 4), 256, 0, s1>>>(p_p1, W_p2, b_p2, p_inl,
                                                       512, INL, 1);
    cudaEventRecord(evJoin, s1);

    // main: attention-energy GEMM on the 10-step window [640,512]x[256,512]
    gemm64_kernel<<<dim3(ATT / 64, (NB * TW) / 64, SK_ATT), dim3(16, 16)>>>(
        p_X2, W_enc, p_C2, NB * TW, ATT, ENC);

    // ---- join ----
    cudaStreamWaitEvent(0, evJoin, 0);

    logit_smax_ctx_kernel<<<NB, 256>>>(lengths, b_enc, conv_prev, W_speed_att,
                                       speed, W_proj, b_proj, out + NB * OUTM, wctx);

    // LSTM layer 0: [64,832] x [4096,832]
    gemm64_kernel<<<dim3(G4 / 64, 1, SK_L0), dim3(16, 16)>>>(p_inl, Wih0, p_g0, NB, G4, INL);
    lstm_gate_kernel<<<(NB * HID + 255) / 256, 256>>>(p_g0, bih0, bhh0, p_h1, HID, SK_L0);

    // LSTM layer 1: [64,1024] x [4096,1024]
    gemm64_kernel<<<dim3(G4 / 64, 1, SK_L1), dim3(16, 16)>>>(p_h1, Wih1, p_g1, NB, G4, HID);
    lstm_gate_kernel<<<(NB * HID + 255) / 256, 256>>>(p_g1, bih1, bhh1, p_cat, CATL, SK_L1);

    // output linear: [64,1536] x [160,1536] -> d_out[0:10240]
    linW_kernel<<<dim3(OUTM / 8, NB / 4), 256>>>(p_cat, W_out, b_out, out,
                                                 CATL, OUTM, 0);
}

// round 16
// speedup vs baseline: 1.8690x; 1.0251x over previous
#include <cuda_runtime.h>
#include <math.h>

// ---------------- problem constants ----------------
#define NB     64      // batch
#define TT     2000
#define TW     10      // attention window (t in [0, 9])
#define ENC    512
#define ATT    256
#define DEC    256
#define SPK    64
#define OOUT   80
#define HID    1024    // 4*DEC
#define G4     4096    // 4*HID
#define INL    832     // ENC + DEC + SPK
#define CATL   1536    // HID + ENC
#define OUTM   160     // O*R
#define XCATK  144     // O + SPK
#define SK_ATT 8       // 512/8  = 64  -> grid 320
#define SK_L0  13      // 832/13 = 64  -> grid 832
#define SK_L1  16      // 1024/16= 64  -> grid 1024

// packed fp32x2 helpers (sm_103a)
#define FMA_F32X2(d, a, b, c) \
    asm("fma.rn.f32x2 %0, %1, %2, %3;" : "=l"(d) : "l"(a), "l"(b), "l"(c))
#define PACK_DUP(d, f) \
    asm("mov.b64 %0, {%1, %1};" : "=l"(d) : "r"(__float_as_uint(f)))

// ---------------- scratch (device globals; no allocs allowed) ----------------
__device__ float d_xcat  [NB * XCATK];
__device__ float d_s1    [NB * DEC];
__device__ float d_p1    [NB * 512];
__device__ float d_sp    [NB * ENC];
__device__ float d_spkatt[NB * ATT];
__device__ float d_X2    [NB * TW * ENC];
__device__ float d_C2p   [SK_ATT * NB * TW * ATT];
__device__ float d_inlstm[NB * INL];
__device__ float d_g0p   [SK_L0 * NB * G4];
__device__ float d_h1    [NB * HID];
__device__ float d_g1p   [SK_L1 * NB * G4];
__device__ float d_deccat[NB * CATL];

// ---------------- kernel 1: gathers / tiny elementwise prep ----------------
__global__ void prep0_kernel(const float* __restrict__ input_dec,
                             const float* __restrict__ spkr,
                             const float* __restrict__ speed,
                             const float* __restrict__ W_sp1,
                             const float* __restrict__ b_sp1,
                             const float* __restrict__ input_enc) {
    int i = blockIdx.x * blockDim.x + threadIdx.x;
    const int N_XCAT = NB * XCATK;             // 9216
    const int N_S1   = NB * DEC;               // 16384
    const int N_SPK  = NB * SPK;               // 4096
    const int N_X24  = NB * TW * ENC / 4;      // 81920 float4s
    if (i < N_XCAT) {
        int n = i / XCATK, c = i % XCATK;
        d_xcat[i] = (c < OOUT) ? input_dec[n * OOUT + c] : spkr[n * SPK + (c - OOUT)];
        return;
    }
    i -= N_XCAT;
    if (i < N_S1) {
        int n = i / DEC, d = i % DEC;
        float v = speed[n] * W_sp1[d] + b_sp1[d];
        d_s1[i] = v > 0.f ? v : 0.f;
        return;
    }
    i -= N_S1;
    if (i < N_SPK) {
        int n = i / SPK, c = i % SPK;
        d_inlstm[n * INL + DEC + ENC + c] = spkr[i];
        return;
    }
    i -= N_SPK;
    if (i < N_X24) {
        const int E4 = ENC / 4;
        int r = i / E4, k4 = i % E4;
        int n = r / TW, t = r % TW;
        ((float4*)d_X2)[i] =
            ((const float4*)input_enc)[((size_t)n * TT + t) * E4 + k4];
    }
}

// ---------------- warp-per-output linear body -------------------------------
__device__ __forceinline__ void lin_warp_body(const float* __restrict__ X,
                                              const float* __restrict__ W,
                                              const float* __restrict__ b,
                                              float* __restrict__ C,
                                              int K, int ldc, int act,
                                              int m, int n0, int lane) {
    const float* wrow = W + (size_t)m * K;
    float a0 = 0.f, a1 = 0.f, a2 = 0.f, a3 = 0.f;
    if ((K & 127) == 0) {
        const float* x0 = X + (size_t)(n0 + 0) * K;
        const float* x1 = X + (size_t)(n0 + 1) * K;
        const float* x2 = X + (size_t)(n0 + 2) * K;
        const float* x3 = X + (size_t)(n0 + 3) * K;
        for (int k = lane * 4; k < K; k += 128) {
            float4 wv = *(const float4*)(wrow + k);
            float4 v;
            v = *(const float4*)(x0 + k);
            a0 += v.x * wv.x + v.y * wv.y + v.z * wv.z + v.w * wv.w;
            v = *(const float4*)(x1 + k);
            a1 += v.x * wv.x + v.y * wv.y + v.z * wv.z + v.w * wv.w;
            v = *(const float4*)(x2 + k);
            a2 += v.x * wv.x + v.y * wv.y + v.z * wv.z + v.w * wv.w;
            v = *(const float4*)(x3 + k);
            a3 += v.x * wv.x + v.y * wv.y + v.z * wv.z + v.w * wv.w;
        }
    } else {
        for (int k = lane; k < K; k += 32) {
            float wv = wrow[k];
            a0 += X[(size_t)(n0 + 0) * K + k] * wv;
            a1 += X[(size_t)(n0 + 1) * K + k] * wv;
            a2 += X[(size_t)(n0 + 2) * K + k] * wv;
            a3 += X[(size_t)(n0 + 3) * K + k] * wv;
        }
    }
#pragma unroll
    for (int off = 16; off > 0; off >>= 1) {
        a0 += __shfl_down_sync(0xffffffffu, a0, off);
        a1 += __shfl_down_sync(0xffffffffu, a1, off);
        a2 += __shfl_down_sync(0xffffffffu, a2, off);
        a3 += __shfl_down_sync(0xffffffffu, a3, off);
    }
    if (lane == 0) {
        float bb = b ? b[m] : 0.f;
        float r[4] = {a0 + bb, a1 + bb, a2 + bb, a3 + bb};
#pragma unroll
        for (int i = 0; i < 4; i++) {
            float v = r[i];
            if (act == 1) v = v > 0.f ? v : 0.f;
            else if (act == 2) v = tanhf(v);
            else if (act == 3) v = v / (1.f + fabsf(v));
            C[(size_t)(n0 + i) * ldc + m] = v;
        }
    }
}

__global__ void linW_kernel(const float* __restrict__ X,
                            const float* __restrict__ W,
                            const float* __restrict__ b,
                            float* __restrict__ C,
                            int K, int ldc, int act) {
    int warp = threadIdx.x >> 5, lane = threadIdx.x & 31;
    lin_warp_body(X, W, b, C, K, ldc, act,
                  blockIdx.x * 8 + warp, blockIdx.y * 4, lane);
}

// three independent small linears in ONE launch (segment dispatch on bx)
__global__ void multiLin_kernel(const float* __restrict__ spkr,
                                const float* __restrict__ W_spkr,
                                const float* __restrict__ W_p1,
                                const float* __restrict__ b_p1,
                                const float* __restrict__ W_sp2,
                                const float* __restrict__ b_sp2) {
    int warp = threadIdx.x >> 5, lane = threadIdx.x & 31;
    int bx = blockIdx.x;
    int n0 = blockIdx.y * 4;
    if (bx < 32) {
        lin_warp_body(spkr, W_spkr, nullptr, d_spkatt, SPK, ATT, 3,
                      bx * 8 + warp, n0, lane);
    } else if (bx < 96) {
        lin_warp_body(d_xcat, W_p1, b_p1, d_p1, XCATK, 512, 1,
                      (bx - 32) * 8 + warp, n0, lane);
    } else {
        lin_warp_body(d_s1, W_sp2, b_sp2, d_sp, DEC, ENC, 2,
                      (bx - 96) * 8 + warp, n0, lane);
    }
}

// ---------------- big GEMM: single-shot K=64 tile, ONE barrier -------------
// Requires K/gridDim.z == 64. Whole 64x64 X and W slabs loaded to smem with
// 8 independent LDG.128 per thread (MLP=8, one L2 latency), then a fully
// unrolled 64-step FFMA2 compute with zero further syncs.
__global__ void __launch_bounds__(256)
gemm64_kernel(const float* __restrict__ X,
              const float* __restrict__ W,
              float* __restrict__ Cp,
              int NN, int M, int K) {
    __shared__ float Xs[64][68];
    __shared__ float Ws[64][68];
    int ks0 = 64 * blockIdx.z;
    int m0 = blockIdx.x * 64;
    int n0 = blockIdx.y * 64;
    int tx = threadIdx.x, ty = threadIdx.y;
    int tid = ty * 16 + tx;
    int lr = tid >> 2;            // 0..63  (matrix row)
    int lk = (tid & 3) * 4;       // 0,4,8,12 (k sub-offset)
    const float* Xp = X + (size_t)(n0 + lr) * K + ks0 + lk;
    const float* Wp = W + (size_t)(m0 + lr) * K + ks0 + lk;

    // load phase: 8 independent 16B loads, then scatter to k-major smem
    float4 xv[4], wv[4];
#pragma unroll
    for (int i = 0; i < 4; i++) {
        xv[i] = *(const float4*)(Xp + 16 * i);
        wv[i] = *(const float4*)(Wp + 16 * i);
    }
#pragma unroll
    for (int i = 0; i < 4; i++) {
        int kb = lk + 16 * i;
        Xs[kb + 0][lr] = xv[i].x; Xs[kb + 1][lr] = xv[i].y;
        Xs[kb + 2][lr] = xv[i].z; Xs[kb + 3][lr] = xv[i].w;
        Ws[kb + 0][lr] = wv[i].x; Ws[kb + 1][lr] = wv[i].y;
        Ws[kb + 2][lr] = wv[i].z; Ws[kb + 3][lr] = wv[i].w;
    }
    __syncthreads();

    unsigned long long acc[4][2];
#pragma unroll
    for (int i = 0; i < 4; i++) { acc[i][0] = 0ull; acc[i][1] = 0ull; }

#pragma unroll
    for (int kb = 0; kb < 4; kb++) {
#pragma unroll
        for (int k = 0; k < 16; k++) {
            int kk = kb * 16 + k;
            float4 xr = *(const float4*)&Xs[kk][4 * ty];
            unsigned long long w01 = *(const unsigned long long*)&Ws[kk][4 * tx];
            unsigned long long w23 = *(const unsigned long long*)&Ws[kk][4 * tx + 2];
            unsigned long long xx;
            PACK_DUP(xx, xr.x);
            FMA_F32X2(acc[0][0], xx, w01, acc[0][0]);
            FMA_F32X2(acc[0][1], xx, w23, acc[0][1]);
            PACK_DUP(xx, xr.y);
            FMA_F32X2(acc[1][0], xx, w01, acc[1][0]);
            FMA_F32X2(acc[1][1], xx, w23, acc[1][1]);
            PACK_DUP(xx, xr.z);
            FMA_F32X2(acc[2][0], xx, w01, acc[2][0]);
            FMA_F32X2(acc[2][1], xx, w23, acc[2][1]);
            PACK_DUP(xx, xr.w);
            FMA_F32X2(acc[3][0], xx, w01, acc[3][0]);
            FMA_F32X2(acc[3][1], xx, w23, acc[3][1]);
        }
    }

    size_t base = (size_t)blockIdx.z * NN * M;
#pragma unroll
    for (int i = 0; i < 4; i++) {
        float4 o;
        unsigned int u0, u1;
        asm("mov.b64 {%0, %1}, %2;" : "=r"(u0), "=r"(u1) : "l"(acc[i][0]));
        o.x = __uint_as_float(u0); o.y = __uint_as_float(u1);
        asm("mov.b64 {%0, %1}, %2;" : "=r"(u0), "=r"(u1) : "l"(acc[i][1]));
        o.z = __uint_as_float(u0); o.w = __uint_as_float(u1);
        *(float4*)&Cp[base + (size_t)(n0 + 4 * ty + i) * M + m0 + 4 * tx] = o;
    }
}

// ---------------- fused logit + windowed softmax + context -----------------
__global__ void logit_smax_ctx_kernel(const int* __restrict__ lengths,
                                      const float* __restrict__ b_enc,
                                      const float* __restrict__ conv_prev,
                                      const float* __restrict__ W_speed_att,
                                      const float* __restrict__ speed,
                                      const float* __restrict__ W_proj,
                                      const float* __restrict__ b_proj,
                                      float* __restrict__ out_ctx,
                                      int wctx) {
    int n = blockIdx.x;
    int a = threadIdx.x;           // 0..255
    int lane = a & 31, warp = a >> 5;
    __shared__ float red[8][TW];
    __shared__ float sm_lg[TW];

    float spd    = speed[n];
    float spk_a  = d_spkatt[n * ATT + a];
    float spda   = spd * W_speed_att[a];
    float wp     = W_proj[a];
    float be     = b_enc[a];

    float p[TW];
#pragma unroll
    for (int t = 0; t < TW; t++) {
        float v = be;
#pragma unroll
        for (int s = 0; s < SK_ATT; s++)
            v += d_C2p[(size_t)s * NB * TW * ATT + (size_t)(n * TW + t) * ATT + a];
        float e = v / (1.f + fabsf(v)) + spk_a + conv_prev[a * 31 + (15 - t)] + spda;
        p[t] = tanhf(e) * wp;
    }
#pragma unroll
    for (int off = 16; off > 0; off >>= 1)
#pragma unroll
        for (int t = 0; t < TW; t++)
            p[t] += __shfl_down_sync(0xffffffffu, p[t], off);
    if (lane == 0)
#pragma unroll
        for (int t = 0; t < TW; t++) red[warp][t] = p[t];
    __syncthreads();
    if (a < TW) {
        float tot = 0.f;
#pragma unroll
        for (int w = 0; w < 8; w++) tot += red[w][a];
        sm_lg[a] = tot + b_proj[0];
    }
    __syncthreads();

    int len = lengths[n];
    int len1 = (len > 1 ? len : 1) - 1;
    int hi = len1 < (TW - 1) ? len1 : (TW - 1);
    float m = -1e30f;
#pragma unroll
    for (int t = 0; t < TW; t++) { float l = sm_lg[t]; if (t <= hi && l > m) m = l; }
    float att[TW]; float s = 0.f;
#pragma unroll
    for (int t = 0; t < TW; t++) {
        float w = (t <= hi) ? __expf(sm_lg[t] - m) : 0.f;
        att[t] = w; s += w;
    }
    float inv = 1.f / fmaxf(s, 1e-12f);
#pragma unroll
    for (int t = 0; t < TW; t++) att[t] *= inv;

#pragma unroll
    for (int it = 0; it < 2; it++) {
        int e = a + it * 256;
        float spv = d_sp[n * ENC + e];
        float acc = 0.f;
#pragma unroll
        for (int t = 0; t < TW; t++)
            acc += att[t] * (d_X2[((size_t)n * TW + t) * ENC + e] + spv);
        d_inlstm[n * INL + DEC + e]  = acc;     // [pre | ctx | spkr]
        d_deccat[n * CATL + HID + e] = acc;     // [h2 | ctx]
        if (wctx) out_ctx[n * ENC + e] = acc;
    }
}

// ---------------- LSTM gate (zero initial state => f gate dead) ------------
__global__ void lstm_gate_kernel(const float* __restrict__ gp,
                                 const float* __restrict__ bih,
                                 const float* __restrict__ bhh,
                                 float* __restrict__ hout,
                                 int out_stride, int S) {
    int idx = blockIdx.x * blockDim.x + threadIdx.x;   // n*HID + j
    if (idx >= NB * HID) return;
    int n = idx / HID, j = idx % HID;
    size_t row = (size_t)n * G4;
    float gi = bih[j]          + bhh[j];
    float gg = bih[2*HID + j]  + bhh[2*HID + j];
    float go = bih[3*HID + j]  + bhh[3*HID + j];
    for (int s = 0; s < S; s++) {
        size_t base = (size_t)s * NB * G4 + row;
        gi += gp[base + j];
        gg += gp[base + 2*HID + j];
        go += gp[base + 3*HID + j];
    }
    float si = 1.f / (1.f + __expf(-gi));
    float so = 1.f / (1.f + __expf(-go));
    float h = so * tanhf(si * tanhf(gg));
    hout[(size_t)n * out_stride + j] = h;
}

extern "C" void kernel_launch(void* const* d_in, const int* in_sizes, int n_in,
                              void* d_out, int out_size) {
    const float* input_enc   = (const float*)d_in[0];
    const float* input_dec   = (const float*)d_in[1];
    const float* spkr        = (const float*)d_in[2];
    const int*   lengths     = (const int*)  d_in[3];
    const float* speed       = (const float*)d_in[4];
    const float* W_enc       = (const float*)d_in[5];
    const float* b_enc       = (const float*)d_in[6];
    const float* W_spkr      = (const float*)d_in[7];
    const float* conv_prev   = (const float*)d_in[8];
    const float* W_speed_att = (const float*)d_in[9];
    const float* W_proj      = (const float*)d_in[10];
    const float* b_proj      = (const float*)d_in[11];
    const float* W_sp1       = (const float*)d_in[12];
    const float* b_sp1       = (const float*)d_in[13];
    const float* W_sp2       = (const float*)d_in[14];
    const float* b_sp2       = (const float*)d_in[15];
    const float* W_p1        = (const float*)d_in[16];
    const float* b_p1        = (const float*)d_in[17];
    const float* W_p2        = (const float*)d_in[18];
    const float* b_p2        = (const float*)d_in[19];
    const float* Wih0        = (const float*)d_in[20];
    const float* bih0        = (const float*)d_in[22];
    const float* bhh0        = (const float*)d_in[23];
    const float* Wih1        = (const float*)d_in[24];
    const float* bih1        = (const float*)d_in[26];
    const float* bhh1        = (const float*)d_in[27];
    const float* W_out       = (const float*)d_in[28];
    const float* b_out       = (const float*)d_in[29];

    float* out = (float*)d_out;
    int wctx = (out_size >= NB * OUTM + NB * ENC) ? 1 : 0;

    static float *p_xcat = nullptr, *p_s1, *p_p1, *p_sp, *p_spk, *p_X2,
                 *p_inl, *p_g0, *p_h1, *p_g1, *p_cat, *p_C2;
    static cudaStream_t s1;
    static cudaEvent_t evFork, evJoin;
    if (!p_xcat) {
        cudaGetSymbolAddress((void**)&p_xcat, d_xcat);
        cudaGetSymbolAddress((void**)&p_s1,   d_s1);
        cudaGetSymbolAddress((void**)&p_p1,   d_p1);
        cudaGetSymbolAddress((void**)&p_sp,   d_sp);
        cudaGetSymbolAddress((void**)&p_spk,  d_spkatt);
        cudaGetSymbolAddress((void**)&p_X2,   d_X2);
        cudaGetSymbolAddress((void**)&p_inl,  d_inlstm);
        cudaGetSymbolAddress((void**)&p_g0,   d_g0p);
        cudaGetSymbolAddress((void**)&p_h1,   d_h1);
        cudaGetSymbolAddress((void**)&p_g1,   d_g1p);
        cudaGetSymbolAddress((void**)&p_cat,  d_deccat);
        cudaGetSymbolAddress((void**)&p_C2,   d_C2p);
        cudaStreamCreateWithFlags(&s1, cudaStreamNonBlocking);
        cudaEventCreateWithFlags(&evFork, cudaEventDisableTiming);
        cudaEventCreateWithFlags(&evJoin, cudaEventDisableTiming);
    }

    int prep_threads = NB * XCATK + NB * DEC + NB * SPK + NB * TW * ENC / 4;
    prep0_kernel<<<(prep_threads + 255) / 256, 256>>>(input_dec, spkr, speed,
                                                      W_sp1, b_sp1, input_enc);

    // ---- fork: small-linear branch on s1, attention GEMM on main stream ----
    cudaEventRecord(evFork, 0);
    cudaStreamWaitEvent(s1, evFork, 0);

    multiLin_kernel<<<dim3(160, NB / 4), 256, 0, s1>>>(spkr, W_spkr,
                                                       W_p1, b_p1, W_sp2, b_sp2);
    linW_kernel<<<dim3(DEC / 8, NB / 4), 256, 0, s1>>>(p_p1, W_p2, b_p2, p_inl,
                                                       512, INL, 1);
    cudaEventRecord(evJoin, s1);

    // main: attention-energy GEMM on the 10-step window [640,512]x[256,512]
    gemm64_kernel<<<dim3(ATT / 64, (NB * TW) / 64, SK_ATT), dim3(16, 16)>>>(
        p_X2, W_enc, p_C2, NB * TW, ATT, ENC);

    // ---- join ----
    cudaStreamWaitEvent(0, evJoin, 0);

    logit_smax_ctx_kernel<<<NB, 256>>>(lengths, b_enc, conv_prev, W_speed_att,
                                       speed, W_proj, b_proj, out + NB * OUTM, wctx);

    // LSTM layer 0: [64,832] x [4096,832]
    gemm64_kernel<<<dim3(G4 / 64, 1, SK_L0), dim3(16, 16)>>>(p_inl, Wih0, p_g0, NB, G4, INL);
    lstm_gate_kernel<<<(NB * HID + 255) / 256, 256>>>(p_g0, bih0, bhh0, p_h1, HID, SK_L0);

    // LSTM layer 1: [64,1024] x [4096,1024]
    gemm64_kernel<<<dim3(G4 / 64, 1, SK_L1), dim3(16, 16)>>>(p_h1, Wih1, p_g1, NB, G4, HID);
    lstm_gate_kernel<<<(NB * HID + 255) / 256, 256>>>(p_g1, bih1, bhh1, p_cat, CATL, SK_L1);

    // output linear: [64,1536] x [160,1536] -> d_out[0:10240]
    linW_kernel<<<dim3(OUTM / 8, NB / 4), 256>>>(p_cat, W_out, b_out, out,
                                                 CATL, OUTM, 0);
}